// round 12
// baseline (speedup 1.0000x reference)
#include <cuda_runtime.h>
#include <cuda_bf16.h>
#include <cstdint>

#define NN 51200
#define EE 819200
#define NQ 512
#define HH 128
#define RR 16
#define NBASE 8
#define CIN 128
#define YC 1024
#define KTOT 1152
#define NPAIR 576
#define NCHUNK 36
#define NBLK 50
#define SENTINEL (-2147483647)
#define GEMM_GRID 296
#define BWORDS 73728       /* per-layer fragment-ordered B: 36*2*128*8 words */

// smem (32-bit words): Ah/Al 2 stages x 128 rows x 20; Bh/Bl 2 stages x 2048 (fragment order)
#define ASTRIDE 20
#define A_PLANE 2560
#define B_PLANE 2048
#define OFF_AL  (2 * A_PLANE)
#define OFF_BH  (4 * A_PLANE)
#define OFF_BL  (4 * A_PLANE + 2 * B_PLANE)
#define SMEMSZ ((4 * A_PLANE + 4 * B_PLANE) * 4)   /* 73728 B */

#define CP_ASYNC16(dst, src) \
    asm volatile("cp.async.cg.shared.global [%0], [%1], 16;" :: "r"(dst), "l"(src))
#define CP_COMMIT() asm volatile("cp.async.commit_group;" ::: "memory")
#define CP_WAIT1()  asm volatile("cp.async.wait_group 1;" ::: "memory")
#define CP_WAIT0()  asm volatile("cp.async.wait_group 0;" ::: "memory")

// ---------------- device scratch ----------------
__device__ float    g_h0[NN * CIN];
__device__ float    g_h1[NN * CIN];
__device__ uint32_t g_hsp0h[NN * 64];
__device__ uint32_t g_hsp0l[NN * 64];
__device__ uint32_t g_hsp1h[NN * 64];
__device__ uint32_t g_hsp1l[NN * 64];
__device__ uint32_t g_yh[(size_t)NN * 512];
__device__ uint32_t g_yl[(size_t)NN * 512];
__device__ uint32_t g_y4h[NQ * 512];
__device__ uint32_t g_y4l[NQ * 512];
__device__ float    g_h4q[NQ * HH];
__device__ uint32_t g_Bsph[4 * BWORDS];
__device__ uint32_t g_Bspl[4 * BWORDS];
__device__ int      g_cntdeg[NN * RR + NN];
__device__ int      g_rowptr[NN + 1];
__device__ int      g_cursor[NN];
__device__ int      g_eidx[EE];
__device__ int2     g_sw[EE];      // (src*RR+etype, weight bits)
__device__ int      g_qo[NQ];
__device__ int      g_scanpub[NBLK];

// ---------------- bf16 split helpers ----------------
__device__ __forceinline__ void split2(float a, float b, uint32_t& hi, uint32_t& lo) {
    __nv_bfloat16 ah = __float2bfloat16_rn(a), bh = __float2bfloat16_rn(b);
    float ar = a - __bfloat162float(ah), br = b - __bfloat162float(bh);
    __nv_bfloat16 al = __float2bfloat16_rn(ar), bl = __float2bfloat16_rn(br);
    hi = ((uint32_t)__bfloat16_as_ushort(bh) << 16) | __bfloat16_as_ushort(ah);
    lo = ((uint32_t)__bfloat16_as_ushort(bl) << 16) | __bfloat16_as_ushort(al);
}

// ---------------- zero counters + scan slots + qlist ----------------
__global__ void k_zero(const int* __restrict__ dq, const int* __restrict__ ptr) {
    int gid = blockIdx.x * blockDim.x + threadIdx.x;
    if (gid < NN * RR + NN) g_cntdeg[gid] = 0;
    if (gid < NBLK) g_scanpub[gid] = SENTINEL;
    if (gid < NQ) g_qo[gid] = dq[gid] + ptr[gid];
}

// ---------------- setup1: h0 fp32 + split, AND per-(dst,rel)/deg counts ----------------
__global__ void k_setup1(const float* __restrict__ x, const int* __restrict__ ent,
                         const int* __restrict__ edst, const int* __restrict__ etyp) {
    int gid = blockIdx.x * blockDim.x + threadIdx.x;
    if (gid < NN * 64) {
        int n = gid >> 6, pr = gid & 63;
        int j0 = 2 * pr, j1 = j0 + 1;
        int e = __ldg(ent + n);
        float v0 = (j0 < 64) ? __ldg(x + n * 64 + j0) : ((e == j0 - 64) ? 1.0f : 0.0f);
        float v1 = (j1 < 64) ? __ldg(x + n * 64 + j1) : ((e == j1 - 64) ? 1.0f : 0.0f);
        *(float2*)(g_h0 + n * CIN + j0) = make_float2(v0, v1);
        uint32_t hi, lo;
        split2(v0, v1, hi, lo);
        g_hsp0h[gid] = hi;
        g_hsp0l[gid] = lo;
    }
    if (gid < EE) {
        int d = edst[gid], t = etyp[gid];
        atomicAdd(&g_cntdeg[d * RR + t], 1);
        atomicAdd(&g_cntdeg[NN * RR + d], 1);
    }
}

// ---------------- chained exclusive scan over deg (50 blocks, all resident) ----------------
__global__ void k_scan1() {
    __shared__ int sd[1024];
    __shared__ int s_prev;
    int b = blockIdx.x, tid = threadIdx.x;
    int gid = b * 1024 + tid;
    int v = g_cntdeg[NN * RR + gid];
    sd[tid] = v;
    __syncthreads();
    for (int off = 1; off < 1024; off <<= 1) {
        int t = (tid >= off) ? sd[tid - off] : 0;
        __syncthreads();
        sd[tid] += t;
        __syncthreads();
    }
    int incl = sd[tid];
    int total = sd[1023];
    if (tid == 0) {
        int prev = 0;
        if (b > 0) {
            while ((prev = atomicAdd(&g_scanpub[b - 1], 0)) == SENTINEL) { }
        }
        s_prev = prev;
        __threadfence();
        atomicExch(&g_scanpub[b], prev + total);
    }
    __syncthreads();
    int e = s_prev + incl - v;
    g_rowptr[gid] = e;
    g_cursor[gid] = e;
    if (gid == 0) g_rowptr[NN] = EE;
}

__global__ void k_fill(const int* __restrict__ edst) {
    int e = blockIdx.x * blockDim.x + threadIdx.x;
    if (e >= EE) return;
    int pos = atomicAdd(&g_cursor[edst[e]], 1);
    g_eidx[pos] = e;
}

// deterministic per-bucket order: sort bucket by edge id (local-array fast path)
__global__ void k_sortfin(const int* __restrict__ esrc, const int* __restrict__ etyp) {
    int n = blockIdx.x * blockDim.x + threadIdx.x;
    if (n >= NN) return;
    int s = g_rowptr[n], t = g_rowptr[n + 1];
    int cnt = t - s;
    if (cnt <= 64) {
        int buf[64];
        for (int i = 0; i < cnt; i++) buf[i] = g_eidx[s + i];
        for (int i = 1; i < cnt; i++) {
            int v = buf[i];
            int j = i - 1;
            while (j >= 0 && buf[j] > v) { buf[j + 1] = buf[j]; j--; }
            buf[j + 1] = v;
        }
        for (int i = 0; i < cnt; i++) {
            int e  = buf[i];
            int et = etyp[e];
            int c  = g_cntdeg[n * RR + et];
            float w = 1.0f / (float)(c < 1 ? 1 : c);
            g_sw[s + i] = make_int2(esrc[e] * RR + et, __float_as_int(w));
        }
    } else {
        for (int i = s + 1; i < t; i++) {
            int v = g_eidx[i];
            int j = i - 1;
            while (j >= s && g_eidx[j] > v) { g_eidx[j + 1] = g_eidx[j]; j--; }
            g_eidx[j + 1] = v;
        }
        for (int i = s; i < t; i++) {
            int e  = g_eidx[i];
            int et = etyp[e];
            int c  = g_cntdeg[n * RR + et];
            float w = 1.0f / (float)(c < 1 ? 1 : c);
            g_sw[i] = make_int2(esrc[e] * RR + et, __float_as_int(w));
        }
    }
}

// ---------------- pre-split weights -> fragment-ordered packed bf16 pairs ----------------
__global__ void k_splitB(const float* __restrict__ r1, const float* __restrict__ b1,
                         const float* __restrict__ r2, const float* __restrict__ b2,
                         const float* __restrict__ r3, const float* __restrict__ b3,
                         const float* __restrict__ r4, const float* __restrict__ b4) {
    int gid = blockIdx.x * blockDim.x + threadIdx.x;
    if (gid >= 4 * NPAIR * 128) return;
    int l = gid / (NPAIR * 128);
    int rem = gid - l * (NPAIR * 128);
    int kp = rem >> 7, c = rem & 127;
    const float* root  = (l == 0) ? r1 : (l == 1) ? r2 : (l == 2) ? r3 : r4;
    const float* bases = (l == 0) ? b1 : (l == 1) ? b2 : (l == 2) ? b3 : b4;
    int k0 = 2 * kp, k1 = k0 + 1;
    float v0 = (k0 < 128) ? root[k0 * HH + c] : bases[(size_t)(k0 - 128) * HH + c];
    float v1 = (k1 < 128) ? root[k1 * HH + c] : bases[(size_t)(k1 - 128) * HH + c];
    uint32_t hi, lo;
    split2(v0, v1, hi, lo);
    int ci = kp >> 4, r16 = kp & 15;
    int ks = r16 >> 3, pp = r16 & 7;
    int slot = (pp < 4) ? (pp * 2) : ((pp - 4) * 2 + 1);
    size_t idx = (size_t)l * BWORDS + (((ci * 2 + ks) * 128 + c) * 8 + slot);
    g_Bsph[idx] = hi;
    g_Bspl[idx] = lo;
}

// ---------------- aggregate-first: 2 warps per node, 64 cols each ----------------
#define AGGR_EDGE2(sv, wv, vv)                                       \
    {                                                                \
        const float* cc = sc + ((sv) & 15) * NBASE;                  \
        _Pragma("unroll")                                            \
        for (int b = 0; b < NBASE; b++) {                            \
            float f = cc[b] * (wv);                                  \
            acc[b].x += f * (vv).x; acc[b].y += f * (vv).y;          \
        }                                                            \
    }

__device__ __forceinline__ void aggr_node2(
    const float* __restrict__ hin, const float* __restrict__ sc,
    int n, int half, int lane, uint32_t* __restrict__ yh, uint32_t* __restrict__ yl,
    size_t orow)
{
    int s = g_rowptr[n], e = g_rowptr[n + 1];
    float2 acc[NBASE];
#pragma unroll
    for (int b = 0; b < NBASE; b++) acc[b] = make_float2(0.f, 0.f);
    int off = half * 64 + (lane << 1);
    int i = s;
    for (; i + 4 <= e; i += 4) {
        int2 p0 = g_sw[i], p1 = g_sw[i + 1], p2 = g_sw[i + 2], p3 = g_sw[i + 3];
        float2 v0 = *(const float2*)(hin + (size_t)(p0.x >> 4) * HH + off);
        float2 v1 = *(const float2*)(hin + (size_t)(p1.x >> 4) * HH + off);
        float2 v2 = *(const float2*)(hin + (size_t)(p2.x >> 4) * HH + off);
        float2 v3 = *(const float2*)(hin + (size_t)(p3.x >> 4) * HH + off);
        AGGR_EDGE2(p0.x, __int_as_float(p0.y), v0)
        AGGR_EDGE2(p1.x, __int_as_float(p1.y), v1)
        AGGR_EDGE2(p2.x, __int_as_float(p2.y), v2)
        AGGR_EDGE2(p3.x, __int_as_float(p3.y), v3)
    }
    for (; i < e; i++) {
        int2 p0 = g_sw[i];
        float2 v0 = *(const float2*)(hin + (size_t)(p0.x >> 4) * HH + off);
        AGGR_EDGE2(p0.x, __int_as_float(p0.y), v0)
    }
    size_t base = orow * 512 + half * 32 + lane;
#pragma unroll
    for (int b = 0; b < NBASE; b++) {
        uint32_t hi, lo;
        split2(acc[b].x, acc[b].y, hi, lo);
        yh[base + b * 64] = hi;
        yl[base + b * 64] = lo;
    }
}

__global__ void __launch_bounds__(512) k_aggr(const float* __restrict__ hin,
                                              const float* __restrict__ comp) {
    __shared__ float sc[RR * NBASE];
    int tid = threadIdx.x;
    if (tid < RR * NBASE) sc[tid] = comp[tid];
    __syncthreads();
    int gw = (blockIdx.x * blockDim.x + tid) >> 5;
    int node = gw >> 1, half = gw & 1, lane = tid & 31;
    if (node >= NN) return;
    aggr_node2(hin, sc, node, half, lane, g_yh, g_yl, (size_t)node);
}

__global__ void __launch_bounds__(512) k_aggr4(const float* __restrict__ hin,
                                               const float* __restrict__ comp) {
    __shared__ float sc[RR * NBASE];
    int tid = threadIdx.x;
    if (tid < RR * NBASE) sc[tid] = comp[tid];
    __syncthreads();
    int gw = (blockIdx.x * blockDim.x + tid) >> 5;
    int q = gw >> 1, half = gw & 1, lane = tid & 31;
    if (q >= NQ) return;
    aggr_node2(hin, sc, g_qo[q], half, lane, g_y4h, g_y4l, (size_t)q);
}

// ---------------- bf16x3 GEMM: cp.async staging + ldmatrix A + fragment B ----------------
__device__ __forceinline__ void mma16(float* c, const uint32_t* a, const uint32_t* b) {
    asm("mma.sync.aligned.m16n8k16.row.col.f32.bf16.bf16.f32 "
        "{%0,%1,%2,%3}, {%4,%5,%6,%7}, {%8,%9}, {%0,%1,%2,%3};"
        : "+f"(c[0]), "+f"(c[1]), "+f"(c[2]), "+f"(c[3])
        : "r"(a[0]), "r"(a[1]), "r"(a[2]), "r"(a[3]), "r"(b[0]), "r"(b[1]));
}

__device__ __forceinline__ void ldsm4(uint32_t* r, uint32_t addr) {
    asm volatile("ldmatrix.sync.aligned.m8n8.x4.shared.b16 {%0,%1,%2,%3}, [%4];"
        : "=r"(r[0]), "=r"(r[1]), "=r"(r[2]), "=r"(r[3]) : "r"(addr));
}

__global__ void __launch_bounds__(512) k_gemm2(
    const uint32_t* __restrict__ A1h, const uint32_t* __restrict__ A1l, // [N x 64]
    const uint32_t* __restrict__ A2h, const uint32_t* __restrict__ A2l, // [M x 512]
    const uint32_t* __restrict__ Bh,  const uint32_t* __restrict__ Bl,  // fragment-ordered
    const int* __restrict__ rowmap, const float* __restrict__ cbias,
    float* __restrict__ Cout, uint32_t* __restrict__ Coh, uint32_t* __restrict__ Col,
    int relu, int ntiles)
{
    extern __shared__ uint32_t sm[];
    uint32_t smb = (uint32_t)__cvta_generic_to_shared(sm);

    int tid = threadIdx.x;
    int wid = tid >> 5, lane = tid & 31;
    int wm = wid >> 2, wn = wid & 3;         // 4x4 warps, warp tile 32x32
    int grp = lane >> 2, tig = lane & 3;

    int r = tid >> 2, q4 = (tid & 3) * 4;
    uint32_t arow_b[2];
#pragma unroll
    for (int mi = 0; mi < 2; mi++)
        arow_b[mi] = (uint32_t)(((wm * 32 + mi * 16 + (lane & 15)) * ASTRIDE) * 4
                                + ((lane & 16) ? 16 : 0));
    int bcol[4];
#pragma unroll
    for (int ni = 0; ni < 4; ni++)
        bcol[ni] = ((wn * 32 + ni * 8 + grp) * 8 + tig * 2);

    // per-stage smem byte addresses for this thread's cp.async destinations
    uint32_t dAh[2], dAl[2], dBh[2], dBl[2];
#pragma unroll
    for (int st = 0; st < 2; st++) {
        dAh[st] = smb + (st * A_PLANE + r * ASTRIDE + q4) * 4;
        dAl[st] = smb + (OFF_AL + st * A_PLANE + r * ASTRIDE + q4) * 4;
        dBh[st] = smb + (OFF_BH + st * B_PLANE + tid * 4) * 4;
        dBl[st] = smb + (OFF_BL + st * B_PLANE + tid * 4) * 4;
    }

    for (int tile = blockIdx.x; tile < ntiles; tile += gridDim.x) {
        int row0 = tile * 128;
        int gr = row0 + r;
        int ar = rowmap ? rowmap[gr] : gr;

        auto ISSUE = [&](int ci) {
            int st = ci & 1;
            const uint32_t *pah, *pal;
            if (ci < 4) {
                size_t ia = (size_t)ar * 64 + ci * 16 + q4;
                pah = A1h + ia; pal = A1l + ia;
            } else {
                size_t ia = (size_t)gr * 512 + (ci * 16 - 64) + q4;
                pah = A2h + ia; pal = A2l + ia;
            }
            CP_ASYNC16(dAh[st], pah);
            CP_ASYNC16(dAl[st], pal);
            size_t ib = (size_t)ci * 2048 + tid * 4;
            CP_ASYNC16(dBh[st], Bh + ib);
            CP_ASYNC16(dBl[st], Bl + ib);
            CP_COMMIT();
        };

        float acc[2][4][4];
#pragma unroll
        for (int mi = 0; mi < 2; mi++)
#pragma unroll
            for (int ni = 0; ni < 4; ni++)
#pragma unroll
                for (int k = 0; k < 4; k++) acc[mi][ni][k] = 0.f;

        ISSUE(0);

        for (int ci = 0; ci < NCHUNK; ci++) {
            int st = ci & 1;
            if (ci + 1 < NCHUNK) { ISSUE(ci + 1); CP_WAIT1(); }
            else                 { CP_WAIT0(); }
            __syncthreads();
            uint32_t baseAh = smb + (st * A_PLANE) * 4;
            uint32_t baseAl = smb + ((OFF_AL + st * A_PLANE)) * 4;
            const uint32_t* sBh = sm + OFF_BH + st * B_PLANE;
            const uint32_t* sBl = sm + OFF_BL + st * B_PLANE;
#pragma unroll
            for (int ks = 0; ks < 2; ks++) {
                uint32_t bh[4][2], bl[4][2];
#pragma unroll
                for (int ni = 0; ni < 4; ni++) {
                    uint2 t0 = *(const uint2*)(sBh + ks * 1024 + bcol[ni]);
                    bh[ni][0] = t0.x; bh[ni][1] = t0.y;
                    uint2 t1 = *(const uint2*)(sBl + ks * 1024 + bcol[ni]);
                    bl[ni][0] = t1.x; bl[ni][1] = t1.y;
                }
#pragma unroll
                for (int mi = 0; mi < 2; mi++) {
                    uint32_t ah[4], al[4];
                    ldsm4(ah, baseAh + arow_b[mi] + ks * 32);
                    ldsm4(al, baseAl + arow_b[mi] + ks * 32);
#pragma unroll
                    for (int ni = 0; ni < 4; ni++) {
                        mma16(acc[mi][ni], ah, bh[ni]);
                        mma16(acc[mi][ni], ah, bl[ni]);
                        mma16(acc[mi][ni], al, bh[ni]);
                    }
                }
            }
            __syncthreads();
        }

        // epilogue: + cbias, optional relu; fp32 out + packed split out
#pragma unroll
        for (int mi = 0; mi < 2; mi++) {
#pragma unroll
            for (int ni = 0; ni < 4; ni++) {
                int gc = wn * 32 + ni * 8 + 2 * tig;
                int rr = row0 + wm * 32 + mi * 16 + grp;
                float b0 = __ldg(cbias + gc), b1 = __ldg(cbias + gc + 1);
                float c00 = acc[mi][ni][0] + b0, c01 = acc[mi][ni][1] + b1;
                float c10 = acc[mi][ni][2] + b0, c11 = acc[mi][ni][3] + b1;
                if (relu) {
                    c00 = fmaxf(c00, 0.f); c01 = fmaxf(c01, 0.f);
                    c10 = fmaxf(c10, 0.f); c11 = fmaxf(c11, 0.f);
                }
                *(float2*)(Cout + (size_t)rr * HH + gc) = make_float2(c00, c01);
                *(float2*)(Cout + (size_t)(rr + 8) * HH + gc) = make_float2(c10, c11);
                if (Coh) {
                    uint32_t hi, lo;
                    split2(c00, c01, hi, lo);
                    Coh[(size_t)rr * 64 + (gc >> 1)] = hi;
                    Col[(size_t)rr * 64 + (gc >> 1)] = lo;
                    split2(c10, c11, hi, lo);
                    Coh[(size_t)(rr + 8) * 64 + (gc >> 1)] = hi;
                    Col[(size_t)(rr + 8) * 64 + (gc >> 1)] = lo;
                }
            }
        }
    }
}

// ---------------- head ----------------
__global__ void k_head(const int* __restrict__ qr,
                       const float* __restrict__ rel, const float* __restrict__ w,
                       const float* __restrict__ b, float* __restrict__ out) {
    int warp = (blockIdx.x * blockDim.x + threadIdx.x) >> 5;
    int lane = threadIdx.x & 31;
    if (warp >= NQ) return;
    const float* hv = g_h4q + (size_t)warp * HH;
    const float* rv = rel + (size_t)qr[warp] * HH;
    float s0 = 0.f, s1 = 0.f;
#pragma unroll
    for (int i = 0; i < 4; i++) {
        int k = lane + 32 * i;
        float a = hv[k], c = rv[k];
        s0 += a * w[k * 2 + 0] + c * w[(HH + k) * 2 + 0];
        s1 += a * w[k * 2 + 1] + c * w[(HH + k) * 2 + 1];
    }
#pragma unroll
    for (int off = 16; off; off >>= 1) {
        s0 += __shfl_xor_sync(0xFFFFFFFFu, s0, off);
        s1 += __shfl_xor_sync(0xFFFFFFFFu, s1, off);
    }
    if (lane == 0) {
        out[warp * 2 + 0] = s0 + b[0];
        out[warp * 2 + 1] = s1 + b[1];
    }
}

// ---------------- launch ----------------
extern "C" void kernel_launch(void* const* d_in, const int* in_sizes, int n_in,
                              void* d_out, int out_size) {
    const float* x    = (const float*)d_in[0];
    const int*   ent  = (const int*)  d_in[1];
    const int*   esrc = (const int*)  d_in[2];
    const int*   edst = (const int*)  d_in[3];
    const int*   etyp = (const int*)  d_in[4];
    const int*   dq   = (const int*)  d_in[5];
    const int*   qr   = (const int*)  d_in[6];
    const int*   ptr  = (const int*)  d_in[7];
    const float* rel  = (const float*)d_in[24];
    const float* lw   = (const float*)d_in[25];
    const float* lb   = (const float*)d_in[26];
    float*       out  = (float*)d_out;

    void* p;
    cudaGetSymbolAddress(&p, g_h0);     float*    h0f = (float*)p;
    cudaGetSymbolAddress(&p, g_h1);     float*    h1f = (float*)p;
    cudaGetSymbolAddress(&p, g_hsp0h);  uint32_t* h0h = (uint32_t*)p;
    cudaGetSymbolAddress(&p, g_hsp0l);  uint32_t* h0l = (uint32_t*)p;
    cudaGetSymbolAddress(&p, g_hsp1h);  uint32_t* h1h = (uint32_t*)p;
    cudaGetSymbolAddress(&p, g_hsp1l);  uint32_t* h1l = (uint32_t*)p;
    cudaGetSymbolAddress(&p, g_yh);     uint32_t* yh  = (uint32_t*)p;
    cudaGetSymbolAddress(&p, g_yl);     uint32_t* yl  = (uint32_t*)p;
    cudaGetSymbolAddress(&p, g_y4h);    uint32_t* y4h = (uint32_t*)p;
    cudaGetSymbolAddress(&p, g_y4l);    uint32_t* y4l = (uint32_t*)p;
    cudaGetSymbolAddress(&p, g_h4q);    float*    h4q = (float*)p;
    cudaGetSymbolAddress(&p, g_Bsph);   uint32_t* bsh = (uint32_t*)p;
    cudaGetSymbolAddress(&p, g_Bspl);   uint32_t* bsl = (uint32_t*)p;
    cudaGetSymbolAddress(&p, g_qo);     int*      qop = (int*)p;

    cudaFuncSetAttribute(k_gemm2, cudaFuncAttributeMaxDynamicSharedMemorySize, SMEMSZ);

    k_zero<<<(NN * RR + NN + 255) / 256, 256>>>(dq, ptr);
    k_setup1<<<(NN * 64 + 255) / 256, 256>>>(x, ent, edst, etyp);
    k_scan1<<<NBLK, 1024>>>();
    k_fill<<<(EE + 255) / 256, 256>>>(edst);
    k_sortfin<<<(NN + 255) / 256, 256>>>(esrc, etyp);
    k_splitB<<<(4 * NPAIR * 128 + 255) / 256, 256>>>(
        (const float*)d_in[10], (const float*)d_in[8],
        (const float*)d_in[14], (const float*)d_in[12],
        (const float*)d_in[18], (const float*)d_in[16],
        (const float*)d_in[22], (const float*)d_in[20]);

    float*    hinf = h0f;  uint32_t* hinh = h0h;  uint32_t* hinl = h0l;
    float*    houtf = h1f; uint32_t* houth = h1h; uint32_t* houtl = h1l;
    for (int l = 0; l < 3; l++) {
        const float* comp = (const float*)d_in[9 + 4 * l];
        const float* cb   = (const float*)d_in[11 + 4 * l];
        k_aggr<<<NN / 8, 512>>>(hinf, comp);
        k_gemm2<<<GEMM_GRID, 512, SMEMSZ>>>(hinh, hinl, yh, yl,
                                            bsh + (size_t)l * BWORDS, bsl + (size_t)l * BWORDS,
                                            nullptr, cb, houtf, houth, houtl, 1, NN / 128);
        float* tf = hinf; hinf = houtf; houtf = tf;
        uint32_t* th = hinh; hinh = houth; houth = th;
        uint32_t* tl = hinl; hinl = houtl; houtl = tl;
    }
    // layer 4: only 512 query rows
    {
        const float* comp = (const float*)d_in[21];
        const float* cb   = (const float*)d_in[23];
        k_aggr4<<<NQ / 8, 512>>>(hinf, comp);
        k_gemm2<<<NQ / 128, 512, SMEMSZ>>>(hinh, hinl, y4h, y4l,
                                           bsh + 3 * (size_t)BWORDS, bsl + 3 * (size_t)BWORDS,
                                           qop, cb, h4q, nullptr, nullptr, 0, NQ / 128);
    }
    k_head<<<(NQ * 32 + 255) / 256, 256>>>(qr, rel, lw, lb, out);
}

// round 13
// speedup vs baseline: 1.1492x; 1.1492x over previous
#include <cuda_runtime.h>
#include <cuda_bf16.h>
#include <cstdint>

#define NN 51200
#define EE 819200
#define NQ 512
#define HH 128
#define RR 16
#define NBASE 8
#define CIN 128
#define YC 1024
#define KTOT 1152
#define NPAIR 576
#define NCHUNK 36
#define NBLK 50
#define SENTINEL (-2147483647)
#define GEMM_GRID 296
#define BWORDS 73728       /* per-layer fragment-ordered B: 36*2*128*8 words */

// smem (32-bit words): Ah/Al 2 stages x 128 rows x 20; Bh/Bl 2 stages x 2048 (fragment order)
#define ASTRIDE 20
#define A_PLANE 2560
#define B_PLANE 2048
#define OFF_AL  (2 * A_PLANE)
#define OFF_BH  (4 * A_PLANE)
#define OFF_BL  (4 * A_PLANE + 2 * B_PLANE)
#define SMEMSZ ((4 * A_PLANE + 4 * B_PLANE) * 4)   /* 73728 B */

// ---------------- device scratch ----------------
__device__ float    g_h0[NN * CIN];
__device__ float    g_h1[NN * CIN];
__device__ uint32_t g_hsp0h[NN * 64];
__device__ uint32_t g_hsp0l[NN * 64];
__device__ uint32_t g_hsp1h[NN * 64];
__device__ uint32_t g_hsp1l[NN * 64];
__device__ uint32_t g_yh[(size_t)NN * 512];
__device__ uint32_t g_yl[(size_t)NN * 512];
__device__ uint32_t g_y4h[NQ * 512];
__device__ uint32_t g_y4l[NQ * 512];
__device__ float    g_h4q[NQ * HH];
__device__ uint32_t g_Bsph[4 * BWORDS];
__device__ uint32_t g_Bspl[4 * BWORDS];
__device__ int      g_cntdeg[NN * RR + NN];
__device__ int      g_rowptr[NN + 1];
__device__ int      g_cursor[NN];
__device__ int      g_eidx[EE];
__device__ int2     g_sw[EE];      // (src*RR+etype, weight bits)
__device__ int      g_qo[NQ];
__device__ int      g_scanpub[NBLK];

// ---------------- bf16 split helpers ----------------
__device__ __forceinline__ void split2(float a, float b, uint32_t& hi, uint32_t& lo) {
    __nv_bfloat16 ah = __float2bfloat16_rn(a), bh = __float2bfloat16_rn(b);
    float ar = a - __bfloat162float(ah), br = b - __bfloat162float(bh);
    __nv_bfloat16 al = __float2bfloat16_rn(ar), bl = __float2bfloat16_rn(br);
    hi = ((uint32_t)__bfloat16_as_ushort(bh) << 16) | __bfloat16_as_ushort(ah);
    lo = ((uint32_t)__bfloat16_as_ushort(bl) << 16) | __bfloat16_as_ushort(al);
}

// ---------------- zero counters + scan slots + qlist ----------------
__global__ void k_zero(const int* __restrict__ dq, const int* __restrict__ ptr) {
    int gid = blockIdx.x * blockDim.x + threadIdx.x;
    if (gid < NN * RR + NN) g_cntdeg[gid] = 0;
    if (gid < NBLK) g_scanpub[gid] = SENTINEL;
    if (gid < NQ) g_qo[gid] = dq[gid] + ptr[gid];
}

// ---------------- setup1: h0 fp32 + split, AND per-(dst,rel)/deg counts ----------------
__global__ void k_setup1(const float* __restrict__ x, const int* __restrict__ ent,
                         const int* __restrict__ edst, const int* __restrict__ etyp) {
    int gid = blockIdx.x * blockDim.x + threadIdx.x;
    if (gid < NN * 64) {
        int n = gid >> 6, pr = gid & 63;
        int j0 = 2 * pr, j1 = j0 + 1;
        int e = __ldg(ent + n);
        float v0 = (j0 < 64) ? __ldg(x + n * 64 + j0) : ((e == j0 - 64) ? 1.0f : 0.0f);
        float v1 = (j1 < 64) ? __ldg(x + n * 64 + j1) : ((e == j1 - 64) ? 1.0f : 0.0f);
        *(float2*)(g_h0 + n * CIN + j0) = make_float2(v0, v1);
        uint32_t hi, lo;
        split2(v0, v1, hi, lo);
        g_hsp0h[gid] = hi;
        g_hsp0l[gid] = lo;
    }
    if (gid < EE) {
        int d = edst[gid], t = etyp[gid];
        atomicAdd(&g_cntdeg[d * RR + t], 1);
        atomicAdd(&g_cntdeg[NN * RR + d], 1);
    }
}

// ---------------- chained exclusive scan over deg (50 blocks, all resident) ----------------
__global__ void k_scan1() {
    __shared__ int sd[1024];
    __shared__ int s_prev;
    int b = blockIdx.x, tid = threadIdx.x;
    int gid = b * 1024 + tid;
    int v = g_cntdeg[NN * RR + gid];
    sd[tid] = v;
    __syncthreads();
    for (int off = 1; off < 1024; off <<= 1) {
        int t = (tid >= off) ? sd[tid - off] : 0;
        __syncthreads();
        sd[tid] += t;
        __syncthreads();
    }
    int incl = sd[tid];
    int total = sd[1023];
    if (tid == 0) {
        int prev = 0;
        if (b > 0) {
            while ((prev = atomicAdd(&g_scanpub[b - 1], 0)) == SENTINEL) { }
        }
        s_prev = prev;
        __threadfence();
        atomicExch(&g_scanpub[b], prev + total);
    }
    __syncthreads();
    int e = s_prev + incl - v;
    g_rowptr[gid] = e;
    g_cursor[gid] = e;
    if (gid == 0) g_rowptr[NN] = EE;
}

__global__ void k_fill(const int* __restrict__ edst) {
    int e = blockIdx.x * blockDim.x + threadIdx.x;
    if (e >= EE) return;
    int pos = atomicAdd(&g_cursor[edst[e]], 1);
    g_eidx[pos] = e;
}

// deterministic per-bucket order: sort bucket by edge id (local-array fast path)
__global__ void k_sortfin(const int* __restrict__ esrc, const int* __restrict__ etyp) {
    int n = blockIdx.x * blockDim.x + threadIdx.x;
    if (n >= NN) return;
    int s = g_rowptr[n], t = g_rowptr[n + 1];
    int cnt = t - s;
    if (cnt <= 64) {
        int buf[64];
        for (int i = 0; i < cnt; i++) buf[i] = g_eidx[s + i];
        for (int i = 1; i < cnt; i++) {
            int v = buf[i];
            int j = i - 1;
            while (j >= 0 && buf[j] > v) { buf[j + 1] = buf[j]; j--; }
            buf[j + 1] = v;
        }
        for (int i = 0; i < cnt; i++) {
            int e  = buf[i];
            int et = etyp[e];
            int c  = g_cntdeg[n * RR + et];
            float w = 1.0f / (float)(c < 1 ? 1 : c);
            g_sw[s + i] = make_int2(esrc[e] * RR + et, __float_as_int(w));
        }
    } else {
        for (int i = s + 1; i < t; i++) {
            int v = g_eidx[i];
            int j = i - 1;
            while (j >= s && g_eidx[j] > v) { g_eidx[j + 1] = g_eidx[j]; j--; }
            g_eidx[j + 1] = v;
        }
        for (int i = s; i < t; i++) {
            int e  = g_eidx[i];
            int et = etyp[e];
            int c  = g_cntdeg[n * RR + et];
            float w = 1.0f / (float)(c < 1 ? 1 : c);
            g_sw[i] = make_int2(esrc[e] * RR + et, __float_as_int(w));
        }
    }
}

// ---------------- pre-split weights -> fragment-ordered packed bf16 pairs ----------------
__global__ void k_splitB(const float* __restrict__ r1, const float* __restrict__ b1,
                         const float* __restrict__ r2, const float* __restrict__ b2,
                         const float* __restrict__ r3, const float* __restrict__ b3,
                         const float* __restrict__ r4, const float* __restrict__ b4) {
    int gid = blockIdx.x * blockDim.x + threadIdx.x;
    if (gid >= 4 * NPAIR * 128) return;
    int l = gid / (NPAIR * 128);
    int rem = gid - l * (NPAIR * 128);
    int kp = rem >> 7, c = rem & 127;
    const float* root  = (l == 0) ? r1 : (l == 1) ? r2 : (l == 2) ? r3 : r4;
    const float* bases = (l == 0) ? b1 : (l == 1) ? b2 : (l == 2) ? b3 : b4;
    int k0 = 2 * kp, k1 = k0 + 1;
    float v0 = (k0 < 128) ? root[k0 * HH + c] : bases[(size_t)(k0 - 128) * HH + c];
    float v1 = (k1 < 128) ? root[k1 * HH + c] : bases[(size_t)(k1 - 128) * HH + c];
    uint32_t hi, lo;
    split2(v0, v1, hi, lo);
    int ci = kp >> 4, r16 = kp & 15;
    int ks = r16 >> 3, pp = r16 & 7;
    int slot = (pp < 4) ? (pp * 2) : ((pp - 4) * 2 + 1);
    size_t idx = (size_t)l * BWORDS + (((ci * 2 + ks) * 128 + c) * 8 + slot);
    g_Bsph[idx] = hi;
    g_Bspl[idx] = lo;
}

// ---------------- aggregate-first: y[n,b,:] = sum_e comp[et,b]*w*h[src,:] ----------------
#define AGGR_EDGE(sv, wv, vv)                                        \
    {                                                                \
        const float* cc = sc + ((sv) & 15) * NBASE;                  \
        _Pragma("unroll")                                            \
        for (int b = 0; b < NBASE; b++) {                            \
            float f = cc[b] * (wv);                                  \
            acc[b].x += f * (vv).x; acc[b].y += f * (vv).y;          \
            acc[b].z += f * (vv).z; acc[b].w += f * (vv).w;          \
        }                                                            \
    }

__device__ __forceinline__ void aggr_node(
    const float* __restrict__ hin, const float* __restrict__ sc,
    int n, int lane, uint32_t* __restrict__ yh, uint32_t* __restrict__ yl, size_t orow)
{
    int s = g_rowptr[n], e = g_rowptr[n + 1];
    float4 acc[NBASE];
#pragma unroll
    for (int b = 0; b < NBASE; b++) acc[b] = make_float4(0.f, 0.f, 0.f, 0.f);
    int i = s;
    int lo4 = lane << 2;
    for (; i + 8 <= e; i += 8) {
        int2 p0 = g_sw[i],     p1 = g_sw[i + 1], p2 = g_sw[i + 2], p3 = g_sw[i + 3];
        int2 p4 = g_sw[i + 4], p5 = g_sw[i + 5], p6 = g_sw[i + 6], p7 = g_sw[i + 7];
        float4 v0 = *(const float4*)(hin + (size_t)(p0.x >> 4) * HH + lo4);
        float4 v1 = *(const float4*)(hin + (size_t)(p1.x >> 4) * HH + lo4);
        float4 v2 = *(const float4*)(hin + (size_t)(p2.x >> 4) * HH + lo4);
        float4 v3 = *(const float4*)(hin + (size_t)(p3.x >> 4) * HH + lo4);
        float4 v4 = *(const float4*)(hin + (size_t)(p4.x >> 4) * HH + lo4);
        float4 v5 = *(const float4*)(hin + (size_t)(p5.x >> 4) * HH + lo4);
        float4 v6 = *(const float4*)(hin + (size_t)(p6.x >> 4) * HH + lo4);
        float4 v7 = *(const float4*)(hin + (size_t)(p7.x >> 4) * HH + lo4);
        AGGR_EDGE(p0.x, __int_as_float(p0.y), v0)
        AGGR_EDGE(p1.x, __int_as_float(p1.y), v1)
        AGGR_EDGE(p2.x, __int_as_float(p2.y), v2)
        AGGR_EDGE(p3.x, __int_as_float(p3.y), v3)
        AGGR_EDGE(p4.x, __int_as_float(p4.y), v4)
        AGGR_EDGE(p5.x, __int_as_float(p5.y), v5)
        AGGR_EDGE(p6.x, __int_as_float(p6.y), v6)
        AGGR_EDGE(p7.x, __int_as_float(p7.y), v7)
    }
    for (; i + 4 <= e; i += 4) {
        int2 p0 = g_sw[i], p1 = g_sw[i + 1], p2 = g_sw[i + 2], p3 = g_sw[i + 3];
        float4 v0 = *(const float4*)(hin + (size_t)(p0.x >> 4) * HH + lo4);
        float4 v1 = *(const float4*)(hin + (size_t)(p1.x >> 4) * HH + lo4);
        float4 v2 = *(const float4*)(hin + (size_t)(p2.x >> 4) * HH + lo4);
        float4 v3 = *(const float4*)(hin + (size_t)(p3.x >> 4) * HH + lo4);
        AGGR_EDGE(p0.x, __int_as_float(p0.y), v0)
        AGGR_EDGE(p1.x, __int_as_float(p1.y), v1)
        AGGR_EDGE(p2.x, __int_as_float(p2.y), v2)
        AGGR_EDGE(p3.x, __int_as_float(p3.y), v3)
    }
    for (; i < e; i++) {
        int2 p0 = g_sw[i];
        float4 v0 = *(const float4*)(hin + (size_t)(p0.x >> 4) * HH + lo4);
        AGGR_EDGE(p0.x, __int_as_float(p0.y), v0)
    }
    size_t base = orow * 512 + (lane << 1);
#pragma unroll
    for (int b = 0; b < NBASE; b++) {
        uint32_t h0, l0, h1, l1;
        split2(acc[b].x, acc[b].y, h0, l0);
        split2(acc[b].z, acc[b].w, h1, l1);
        *(uint2*)(yh + base + b * 64) = make_uint2(h0, h1);
        *(uint2*)(yl + base + b * 64) = make_uint2(l0, l1);
    }
}

__global__ void __launch_bounds__(256) k_aggr(const float* __restrict__ hin,
                                              const float* __restrict__ comp) {
    __shared__ float sc[RR * NBASE];
    int tid = threadIdx.x;
    if (tid < RR * NBASE) sc[tid] = comp[tid];
    __syncthreads();
    int warp = (blockIdx.x * blockDim.x + tid) >> 5;
    int lane = tid & 31;
    if (warp >= NN) return;
    aggr_node(hin, sc, warp, lane, g_yh, g_yl, (size_t)warp);
}

__global__ void __launch_bounds__(256) k_aggr4(const float* __restrict__ hin,
                                               const float* __restrict__ comp) {
    __shared__ float sc[RR * NBASE];
    int tid = threadIdx.x;
    if (tid < RR * NBASE) sc[tid] = comp[tid];
    __syncthreads();
    int warp = (blockIdx.x * blockDim.x + tid) >> 5;
    int lane = tid & 31;
    if (warp >= NQ) return;
    aggr_node(hin, sc, g_qo[warp], lane, g_y4h, g_y4l, (size_t)warp);
}

// ---------------- bf16x3 GEMM: ldmatrix A + fragment-ordered B (R11 structure) ----------------
__device__ __forceinline__ void mma16(float* c, const uint32_t* a, const uint32_t* b) {
    asm("mma.sync.aligned.m16n8k16.row.col.f32.bf16.bf16.f32 "
        "{%0,%1,%2,%3}, {%4,%5,%6,%7}, {%8,%9}, {%0,%1,%2,%3};"
        : "+f"(c[0]), "+f"(c[1]), "+f"(c[2]), "+f"(c[3])
        : "r"(a[0]), "r"(a[1]), "r"(a[2]), "r"(a[3]), "r"(b[0]), "r"(b[1]));
}

__device__ __forceinline__ void ldsm4(uint32_t* r, uint32_t addr) {
    asm volatile("ldmatrix.sync.aligned.m8n8.x4.shared.b16 {%0,%1,%2,%3}, [%4];"
        : "=r"(r[0]), "=r"(r[1]), "=r"(r[2]), "=r"(r[3]) : "r"(addr));
}

__global__ void __launch_bounds__(512) k_gemm2(
    const uint32_t* __restrict__ A1h, const uint32_t* __restrict__ A1l, // [N x 64]
    const uint32_t* __restrict__ A2h, const uint32_t* __restrict__ A2l, // [M x 512]
    const uint32_t* __restrict__ Bh,  const uint32_t* __restrict__ Bl,  // fragment-ordered
    const int* __restrict__ rowmap, const float* __restrict__ cbias,
    float* __restrict__ Cout, uint32_t* __restrict__ Coh, uint32_t* __restrict__ Col,
    int relu, int ntiles)
{
    extern __shared__ uint32_t sm[];
    uint32_t smb = (uint32_t)__cvta_generic_to_shared(sm);

    int tid = threadIdx.x;
    int wid = tid >> 5, lane = tid & 31;
    int wm = wid >> 2, wn = wid & 3;         // 4x4 warps, warp tile 32x32
    int grp = lane >> 2, tig = lane & 3;

    int r = tid >> 2, q4 = (tid & 3) * 4;
    uint32_t arow_b[2];
#pragma unroll
    for (int mi = 0; mi < 2; mi++)
        arow_b[mi] = (uint32_t)(((wm * 32 + mi * 16 + (lane & 15)) * ASTRIDE) * 4
                                + ((lane & 16) ? 16 : 0));
    int bcol[4];
#pragma unroll
    for (int ni = 0; ni < 4; ni++)
        bcol[ni] = ((wn * 32 + ni * 8 + grp) * 8 + tig * 2);

    for (int tile = blockIdx.x; tile < ntiles; tile += gridDim.x) {
        int row0 = tile * 128;
        int gr = row0 + r;
        int ar = rowmap ? rowmap[gr] : gr;

        uint4 avh, avl, bvh, bvl;

        auto LOAD = [&](int ci) {
            if (ci < 4) {
                size_t ia = (size_t)ar * 64 + ci * 16 + q4;
                avh = *(const uint4*)(A1h + ia);
                avl = *(const uint4*)(A1l + ia);
            } else {
                size_t ia = (size_t)gr * 512 + (ci * 16 - 64) + q4;
                avh = *(const uint4*)(A2h + ia);
                avl = *(const uint4*)(A2l + ia);
            }
            size_t ib = (size_t)ci * 2048 + tid * 4;
            bvh = *(const uint4*)(Bh + ib);
            bvl = *(const uint4*)(Bl + ib);
        };
        auto STORE = [&](int st) {
            *(uint4*)(sm + st * A_PLANE + r * ASTRIDE + q4)          = avh;
            *(uint4*)(sm + OFF_AL + st * A_PLANE + r * ASTRIDE + q4) = avl;
            *(uint4*)(sm + OFF_BH + st * B_PLANE + tid * 4)          = bvh;
            *(uint4*)(sm + OFF_BL + st * B_PLANE + tid * 4)          = bvl;
        };

        float acc[2][4][4];
#pragma unroll
        for (int mi = 0; mi < 2; mi++)
#pragma unroll
            for (int ni = 0; ni < 4; ni++)
#pragma unroll
                for (int k = 0; k < 4; k++) acc[mi][ni][k] = 0.f;

        LOAD(0);
        STORE(0);
        __syncthreads();

        for (int ci = 0; ci < NCHUNK; ci++) {
            int st = ci & 1;
            if (ci + 1 < NCHUNK) LOAD(ci + 1);
            uint32_t baseAh = smb + (st * A_PLANE) * 4;
            uint32_t baseAl = smb + ((OFF_AL + st * A_PLANE)) * 4;
            const uint32_t* sBh = sm + OFF_BH + st * B_PLANE;
            const uint32_t* sBl = sm + OFF_BL + st * B_PLANE;
#pragma unroll
            for (int ks = 0; ks < 2; ks++) {
                uint32_t bh[4][2], bl[4][2];
#pragma unroll
                for (int ni = 0; ni < 4; ni++) {
                    uint2 t0 = *(const uint2*)(sBh + ks * 1024 + bcol[ni]);
                    bh[ni][0] = t0.x; bh[ni][1] = t0.y;
                    uint2 t1 = *(const uint2*)(sBl + ks * 1024 + bcol[ni]);
                    bl[ni][0] = t1.x; bl[ni][1] = t1.y;
                }
#pragma unroll
                for (int mi = 0; mi < 2; mi++) {
                    uint32_t ah[4], al[4];
                    ldsm4(ah, baseAh + arow_b[mi] + ks * 32);
                    ldsm4(al, baseAl + arow_b[mi] + ks * 32);
#pragma unroll
                    for (int ni = 0; ni < 4; ni++) {
                        mma16(acc[mi][ni], ah, bh[ni]);
                        mma16(acc[mi][ni], ah, bl[ni]);
                        mma16(acc[mi][ni], al, bh[ni]);
                    }
                }
            }
            if (ci + 1 < NCHUNK) STORE((ci + 1) & 1);
            __syncthreads();
        }

        // epilogue: + cbias, optional relu; fp32 out + packed split out
#pragma unroll
        for (int mi = 0; mi < 2; mi++) {
#pragma unroll
            for (int ni = 0; ni < 4; ni++) {
                int gc = wn * 32 + ni * 8 + 2 * tig;
                int rr = row0 + wm * 32 + mi * 16 + grp;
                float b0 = __ldg(cbias + gc), b1 = __ldg(cbias + gc + 1);
                float c00 = acc[mi][ni][0] + b0, c01 = acc[mi][ni][1] + b1;
                float c10 = acc[mi][ni][2] + b0, c11 = acc[mi][ni][3] + b1;
                if (relu) {
                    c00 = fmaxf(c00, 0.f); c01 = fmaxf(c01, 0.f);
                    c10 = fmaxf(c10, 0.f); c11 = fmaxf(c11, 0.f);
                }
                *(float2*)(Cout + (size_t)rr * HH + gc) = make_float2(c00, c01);
                *(float2*)(Cout + (size_t)(rr + 8) * HH + gc) = make_float2(c10, c11);
                if (Coh) {
                    uint32_t hi, lo;
                    split2(c00, c01, hi, lo);
                    Coh[(size_t)rr * 64 + (gc >> 1)] = hi;
                    Col[(size_t)rr * 64 + (gc >> 1)] = lo;
                    split2(c10, c11, hi, lo);
                    Coh[(size_t)(rr + 8) * 64 + (gc >> 1)] = hi;
                    Col[(size_t)(rr + 8) * 64 + (gc >> 1)] = lo;
                }
            }
        }
    }
}

// ---------------- head ----------------
__global__ void k_head(const int* __restrict__ qr,
                       const float* __restrict__ rel, const float* __restrict__ w,
                       const float* __restrict__ b, float* __restrict__ out) {
    int warp = (blockIdx.x * blockDim.x + threadIdx.x) >> 5;
    int lane = threadIdx.x & 31;
    if (warp >= NQ) return;
    const float* hv = g_h4q + (size_t)warp * HH;
    const float* rv = rel + (size_t)qr[warp] * HH;
    float s0 = 0.f, s1 = 0.f;
#pragma unroll
    for (int i = 0; i < 4; i++) {
        int k = lane + 32 * i;
        float a = hv[k], c = rv[k];
        s0 += a * w[k * 2 + 0] + c * w[(HH + k) * 2 + 0];
        s1 += a * w[k * 2 + 1] + c * w[(HH + k) * 2 + 1];
    }
#pragma unroll
    for (int off = 16; off; off >>= 1) {
        s0 += __shfl_xor_sync(0xFFFFFFFFu, s0, off);
        s1 += __shfl_xor_sync(0xFFFFFFFFu, s1, off);
    }
    if (lane == 0) {
        out[warp * 2 + 0] = s0 + b[0];
        out[warp * 2 + 1] = s1 + b[1];
    }
}

// ---------------- launch ----------------
extern "C" void kernel_launch(void* const* d_in, const int* in_sizes, int n_in,
                              void* d_out, int out_size) {
    const float* x    = (const float*)d_in[0];
    const int*   ent  = (const int*)  d_in[1];
    const int*   esrc = (const int*)  d_in[2];
    const int*   edst = (const int*)  d_in[3];
    const int*   etyp = (const int*)  d_in[4];
    const int*   dq   = (const int*)  d_in[5];
    const int*   qr   = (const int*)  d_in[6];
    const int*   ptr  = (const int*)  d_in[7];
    const float* rel  = (const float*)d_in[24];
    const float* lw   = (const float*)d_in[25];
    const float* lb   = (const float*)d_in[26];
    float*       out  = (float*)d_out;

    void* p;
    cudaGetSymbolAddress(&p, g_h0);     float*    h0f = (float*)p;
    cudaGetSymbolAddress(&p, g_h1);     float*    h1f = (float*)p;
    cudaGetSymbolAddress(&p, g_hsp0h);  uint32_t* h0h = (uint32_t*)p;
    cudaGetSymbolAddress(&p, g_hsp0l);  uint32_t* h0l = (uint32_t*)p;
    cudaGetSymbolAddress(&p, g_hsp1h);  uint32_t* h1h = (uint32_t*)p;
    cudaGetSymbolAddress(&p, g_hsp1l);  uint32_t* h1l = (uint32_t*)p;
    cudaGetSymbolAddress(&p, g_yh);     uint32_t* yh  = (uint32_t*)p;
    cudaGetSymbolAddress(&p, g_yl);     uint32_t* yl  = (uint32_t*)p;
    cudaGetSymbolAddress(&p, g_y4h);    uint32_t* y4h = (uint32_t*)p;
    cudaGetSymbolAddress(&p, g_y4l);    uint32_t* y4l = (uint32_t*)p;
    cudaGetSymbolAddress(&p, g_h4q);    float*    h4q = (float*)p;
    cudaGetSymbolAddress(&p, g_Bsph);   uint32_t* bsh = (uint32_t*)p;
    cudaGetSymbolAddress(&p, g_Bspl);   uint32_t* bsl = (uint32_t*)p;
    cudaGetSymbolAddress(&p, g_qo);     int*      qop = (int*)p;

    cudaFuncSetAttribute(k_gemm2, cudaFuncAttributeMaxDynamicSharedMemorySize, SMEMSZ);

    k_zero<<<(NN * RR + NN + 255) / 256, 256>>>(dq, ptr);
    k_setup1<<<(NN * 64 + 255) / 256, 256>>>(x, ent, edst, etyp);
    k_scan1<<<NBLK, 1024>>>();
    k_fill<<<(EE + 255) / 256, 256>>>(edst);
    k_sortfin<<<(NN + 255) / 256, 256>>>(esrc, etyp);
    k_splitB<<<(4 * NPAIR * 128 + 255) / 256, 256>>>(
        (const float*)d_in[10], (const float*)d_in[8],
        (const float*)d_in[14], (const float*)d_in[12],
        (const float*)d_in[18], (const float*)d_in[16],
        (const float*)d_in[22], (const float*)d_in[20]);

    float*    hinf = h0f;  uint32_t* hinh = h0h;  uint32_t* hinl = h0l;
    float*    houtf = h1f; uint32_t* houth = h1h; uint32_t* houtl = h1l;
    for (int l = 0; l < 3; l++) {
        const float* comp = (const float*)d_in[9 + 4 * l];
        const float* cb   = (const float*)d_in[11 + 4 * l];
        k_aggr<<<NN / 8, 256>>>(hinf, comp);
        k_gemm2<<<GEMM_GRID, 512, SMEMSZ>>>(hinh, hinl, yh, yl,
                                            bsh + (size_t)l * BWORDS, bsl + (size_t)l * BWORDS,
                                            nullptr, cb, houtf, houth, houtl, 1, NN / 128);
        float* tf = hinf; hinf = houtf; houtf = tf;
        uint32_t* th = hinh; hinh = houth; houth = th;
        uint32_t* tl = hinl; hinl = houtl; houtl = tl;
    }
    // layer 4: only 512 query rows
    {
        const float* comp = (const float*)d_in[21];
        const float* cb   = (const float*)d_in[23];
        k_aggr4<<<NQ / 8, 256>>>(hinf, comp);
        k_gemm2<<<NQ / 128, 512, SMEMSZ>>>(hinh, hinl, y4h, y4l,
                                           bsh + 3 * (size_t)BWORDS, bsl + 3 * (size_t)BWORDS,
                                           qop, cb, h4q, nullptr, nullptr, 0, NQ / 128);
    }
    k_head<<<(NQ * 32 + 255) / 256, 256>>>(qr, rel, lw, lb, out);
}

// round 14
// speedup vs baseline: 1.1516x; 1.0021x over previous
#include <cuda_runtime.h>
#include <cuda_bf16.h>
#include <cstdint>

#define NN 51200
#define EE 819200
#define NQ 512
#define HH 128
#define RR 16
#define NBASE 8
#define CIN 128
#define YC 1024
#define KTOT 1152
#define NPAIR 576
#define NCHUNK 36
#define NBLK 50
#define SENTINEL (-2147483647)
#define GEMM_GRID 296
#define BWORDS 73728       /* per-layer fragment-ordered B: 36*2*128*8 words */

// smem (32-bit words): Ah/Al 2 stages x 128 rows x 20; Bh/Bl 2 stages x 2048 (fragment order)
#define ASTRIDE 20
#define A_PLANE 2560
#define B_PLANE 2048
#define OFF_AL  (2 * A_PLANE)
#define OFF_BH  (4 * A_PLANE)
#define OFF_BL  (4 * A_PLANE + 2 * B_PLANE)
#define SMEMSZ ((4 * A_PLANE + 4 * B_PLANE) * 4)   /* 73728 B */

// ---------------- device scratch ----------------
__device__ float    g_h0[NN * CIN];
__device__ float    g_h1[NN * CIN];
__device__ uint32_t g_hsp0h[NN * 64];
__device__ uint32_t g_hsp0l[NN * 64];
__device__ uint32_t g_hsp1h[NN * 64];
__device__ uint32_t g_hsp1l[NN * 64];
__device__ uint32_t g_yh[(size_t)NN * 512];
__device__ uint32_t g_yl[(size_t)NN * 512];
__device__ uint32_t g_y4h[NQ * 512];
__device__ uint32_t g_y4l[NQ * 512];
__device__ float    g_h4q[NQ * HH];
__device__ uint32_t g_Bsph[4 * BWORDS];
__device__ uint32_t g_Bspl[4 * BWORDS];
__device__ int      g_cntdeg[NN * RR + NN];
__device__ int      g_rowptr[NN + 1];
__device__ int      g_cursor[NN];
__device__ int      g_eidx[EE];
__device__ int2     g_sw[EE];      // (src*RR+etype, weight bits)
__device__ int      g_qo[NQ];
__device__ int      g_scanpub[NBLK];

// ---------------- bf16 split helpers ----------------
__device__ __forceinline__ void split2(float a, float b, uint32_t& hi, uint32_t& lo) {
    __nv_bfloat16 ah = __float2bfloat16_rn(a), bh = __float2bfloat16_rn(b);
    float ar = a - __bfloat162float(ah), br = b - __bfloat162float(bh);
    __nv_bfloat16 al = __float2bfloat16_rn(ar), bl = __float2bfloat16_rn(br);
    hi = ((uint32_t)__bfloat16_as_ushort(bh) << 16) | __bfloat16_as_ushort(ah);
    lo = ((uint32_t)__bfloat16_as_ushort(bl) << 16) | __bfloat16_as_ushort(al);
}

// ---------------- zero counters + scan slots + qlist ----------------
__global__ void k_zero(const int* __restrict__ dq, const int* __restrict__ ptr) {
    int gid = blockIdx.x * blockDim.x + threadIdx.x;
    if (gid < NN * RR + NN) g_cntdeg[gid] = 0;
    if (gid < NBLK) g_scanpub[gid] = SENTINEL;
    if (gid < NQ) g_qo[gid] = dq[gid] + ptr[gid];
}

// ---------------- setup1: h0 fp32 + split, AND per-(dst,rel)/deg counts ----------------
__global__ void k_setup1(const float* __restrict__ x, const int* __restrict__ ent,
                         const int* __restrict__ edst, const int* __restrict__ etyp) {
    int gid = blockIdx.x * blockDim.x + threadIdx.x;
    if (gid < NN * 64) {
        int n = gid >> 6, pr = gid & 63;
        int j0 = 2 * pr, j1 = j0 + 1;
        int e = __ldg(ent + n);
        float v0 = (j0 < 64) ? __ldg(x + n * 64 + j0) : ((e == j0 - 64) ? 1.0f : 0.0f);
        float v1 = (j1 < 64) ? __ldg(x + n * 64 + j1) : ((e == j1 - 64) ? 1.0f : 0.0f);
        *(float2*)(g_h0 + n * CIN + j0) = make_float2(v0, v1);
        uint32_t hi, lo;
        split2(v0, v1, hi, lo);
        __stcs(&g_hsp0h[gid], hi);
        __stcs(&g_hsp0l[gid], lo);
    }
    if (gid < EE) {
        int d = edst[gid], t = etyp[gid];
        atomicAdd(&g_cntdeg[d * RR + t], 1);
        atomicAdd(&g_cntdeg[NN * RR + d], 1);
    }
}

// ---------------- chained exclusive scan over deg (50 blocks, all resident) ----------------
__global__ void k_scan1() {
    __shared__ int sd[1024];
    __shared__ int s_prev;
    int b = blockIdx.x, tid = threadIdx.x;
    int gid = b * 1024 + tid;
    int v = g_cntdeg[NN * RR + gid];
    sd[tid] = v;
    __syncthreads();
    for (int off = 1; off < 1024; off <<= 1) {
        int t = (tid >= off) ? sd[tid - off] : 0;
        __syncthreads();
        sd[tid] += t;
        __syncthreads();
    }
    int incl = sd[tid];
    int total = sd[1023];
    if (tid == 0) {
        int prev = 0;
        if (b > 0) {
            while ((prev = atomicAdd(&g_scanpub[b - 1], 0)) == SENTINEL) { }
        }
        s_prev = prev;
        __threadfence();
        atomicExch(&g_scanpub[b], prev + total);
    }
    __syncthreads();
    int e = s_prev + incl - v;
    g_rowptr[gid] = e;
    g_cursor[gid] = e;
    if (gid == 0) g_rowptr[NN] = EE;
}

__global__ void k_fill(const int* __restrict__ edst) {
    int e = blockIdx.x * blockDim.x + threadIdx.x;
    if (e >= EE) return;
    int pos = atomicAdd(&g_cursor[edst[e]], 1);
    g_eidx[pos] = e;
}

// deterministic per-bucket order: sort bucket by edge id (local-array fast path)
__global__ void k_sortfin(const int* __restrict__ esrc, const int* __restrict__ etyp) {
    int n = blockIdx.x * blockDim.x + threadIdx.x;
    if (n >= NN) return;
    int s = g_rowptr[n], t = g_rowptr[n + 1];
    int cnt = t - s;
    if (cnt <= 64) {
        int buf[64];
        for (int i = 0; i < cnt; i++) buf[i] = g_eidx[s + i];
        for (int i = 1; i < cnt; i++) {
            int v = buf[i];
            int j = i - 1;
            while (j >= 0 && buf[j] > v) { buf[j + 1] = buf[j]; j--; }
            buf[j + 1] = v;
        }
        for (int i = 0; i < cnt; i++) {
            int e  = buf[i];
            int et = etyp[e];
            int c  = g_cntdeg[n * RR + et];
            float w = 1.0f / (float)(c < 1 ? 1 : c);
            g_sw[s + i] = make_int2(esrc[e] * RR + et, __float_as_int(w));
        }
    } else {
        for (int i = s + 1; i < t; i++) {
            int v = g_eidx[i];
            int j = i - 1;
            while (j >= s && g_eidx[j] > v) { g_eidx[j + 1] = g_eidx[j]; j--; }
            g_eidx[j + 1] = v;
        }
        for (int i = s; i < t; i++) {
            int e  = g_eidx[i];
            int et = etyp[e];
            int c  = g_cntdeg[n * RR + et];
            float w = 1.0f / (float)(c < 1 ? 1 : c);
            g_sw[i] = make_int2(esrc[e] * RR + et, __float_as_int(w));
        }
    }
}

// ---------------- pre-split weights -> fragment-ordered packed bf16 pairs ----------------
__global__ void k_splitB(const float* __restrict__ r1, const float* __restrict__ b1,
                         const float* __restrict__ r2, const float* __restrict__ b2,
                         const float* __restrict__ r3, const float* __restrict__ b3,
                         const float* __restrict__ r4, const float* __restrict__ b4) {
    int gid = blockIdx.x * blockDim.x + threadIdx.x;
    if (gid >= 4 * NPAIR * 128) return;
    int l = gid / (NPAIR * 128);
    int rem = gid - l * (NPAIR * 128);
    int kp = rem >> 7, c = rem & 127;
    const float* root  = (l == 0) ? r1 : (l == 1) ? r2 : (l == 2) ? r3 : r4;
    const float* bases = (l == 0) ? b1 : (l == 1) ? b2 : (l == 2) ? b3 : b4;
    int k0 = 2 * kp, k1 = k0 + 1;
    float v0 = (k0 < 128) ? root[k0 * HH + c] : bases[(size_t)(k0 - 128) * HH + c];
    float v1 = (k1 < 128) ? root[k1 * HH + c] : bases[(size_t)(k1 - 128) * HH + c];
    uint32_t hi, lo;
    split2(v0, v1, hi, lo);
    int ci = kp >> 4, r16 = kp & 15;
    int ks = r16 >> 3, pp = r16 & 7;
    int slot = (pp < 4) ? (pp * 2) : ((pp - 4) * 2 + 1);
    size_t idx = (size_t)l * BWORDS + (((ci * 2 + ks) * 128 + c) * 8 + slot);
    g_Bsph[idx] = hi;
    g_Bspl[idx] = lo;
}

// ---------------- aggregate-first: y[n,b,:] = sum_e comp[et,b]*w*h[src,:] ----------------
#define AGGR_EDGE(sv, wv, vv)                                        \
    {                                                                \
        const float* cc = sc + ((sv) & 15) * NBASE;                  \
        _Pragma("unroll")                                            \
        for (int b = 0; b < NBASE; b++) {                            \
            float f = cc[b] * (wv);                                  \
            acc[b].x += f * (vv).x; acc[b].y += f * (vv).y;          \
            acc[b].z += f * (vv).z; acc[b].w += f * (vv).w;          \
        }                                                            \
    }

__device__ __forceinline__ void aggr_node(
    const float* __restrict__ hin, const float* __restrict__ sc,
    int n, int lane, uint32_t* __restrict__ yh, uint32_t* __restrict__ yl, size_t orow)
{
    int s = g_rowptr[n], e = g_rowptr[n + 1];
    float4 acc[NBASE];
#pragma unroll
    for (int b = 0; b < NBASE; b++) acc[b] = make_float4(0.f, 0.f, 0.f, 0.f);
    int i = s;
    int lo4 = lane << 2;
    for (; i + 8 <= e; i += 8) {
        int2 p0 = g_sw[i],     p1 = g_sw[i + 1], p2 = g_sw[i + 2], p3 = g_sw[i + 3];
        int2 p4 = g_sw[i + 4], p5 = g_sw[i + 5], p6 = g_sw[i + 6], p7 = g_sw[i + 7];
        float4 v0 = *(const float4*)(hin + (size_t)(p0.x >> 4) * HH + lo4);
        float4 v1 = *(const float4*)(hin + (size_t)(p1.x >> 4) * HH + lo4);
        float4 v2 = *(const float4*)(hin + (size_t)(p2.x >> 4) * HH + lo4);
        float4 v3 = *(const float4*)(hin + (size_t)(p3.x >> 4) * HH + lo4);
        float4 v4 = *(const float4*)(hin + (size_t)(p4.x >> 4) * HH + lo4);
        float4 v5 = *(const float4*)(hin + (size_t)(p5.x >> 4) * HH + lo4);
        float4 v6 = *(const float4*)(hin + (size_t)(p6.x >> 4) * HH + lo4);
        float4 v7 = *(const float4*)(hin + (size_t)(p7.x >> 4) * HH + lo4);
        AGGR_EDGE(p0.x, __int_as_float(p0.y), v0)
        AGGR_EDGE(p1.x, __int_as_float(p1.y), v1)
        AGGR_EDGE(p2.x, __int_as_float(p2.y), v2)
        AGGR_EDGE(p3.x, __int_as_float(p3.y), v3)
        AGGR_EDGE(p4.x, __int_as_float(p4.y), v4)
        AGGR_EDGE(p5.x, __int_as_float(p5.y), v5)
        AGGR_EDGE(p6.x, __int_as_float(p6.y), v6)
        AGGR_EDGE(p7.x, __int_as_float(p7.y), v7)
    }
    for (; i + 4 <= e; i += 4) {
        int2 p0 = g_sw[i], p1 = g_sw[i + 1], p2 = g_sw[i + 2], p3 = g_sw[i + 3];
        float4 v0 = *(const float4*)(hin + (size_t)(p0.x >> 4) * HH + lo4);
        float4 v1 = *(const float4*)(hin + (size_t)(p1.x >> 4) * HH + lo4);
        float4 v2 = *(const float4*)(hin + (size_t)(p2.x >> 4) * HH + lo4);
        float4 v3 = *(const float4*)(hin + (size_t)(p3.x >> 4) * HH + lo4);
        AGGR_EDGE(p0.x, __int_as_float(p0.y), v0)
        AGGR_EDGE(p1.x, __int_as_float(p1.y), v1)
        AGGR_EDGE(p2.x, __int_as_float(p2.y), v2)
        AGGR_EDGE(p3.x, __int_as_float(p3.y), v3)
    }
    for (; i < e; i++) {
        int2 p0 = g_sw[i];
        float4 v0 = *(const float4*)(hin + (size_t)(p0.x >> 4) * HH + lo4);
        AGGR_EDGE(p0.x, __int_as_float(p0.y), v0)
    }
    size_t base = orow * 512 + (lane << 1);
#pragma unroll
    for (int b = 0; b < NBASE; b++) {
        uint32_t h0, l0, h1, l1;
        split2(acc[b].x, acc[b].y, h0, l0);
        split2(acc[b].z, acc[b].w, h1, l1);
        __stcs((uint2*)(yh + base + b * 64), make_uint2(h0, h1));
        __stcs((uint2*)(yl + base + b * 64), make_uint2(l0, l1));
    }
}

__global__ void __launch_bounds__(256) k_aggr(const float* __restrict__ hin,
                                              const float* __restrict__ comp) {
    __shared__ float sc[RR * NBASE];
    int tid = threadIdx.x;
    if (tid < RR * NBASE) sc[tid] = comp[tid];
    __syncthreads();
    int warp = (blockIdx.x * blockDim.x + tid) >> 5;
    int lane = tid & 31;
    if (warp >= NN) return;
    aggr_node(hin, sc, warp, lane, g_yh, g_yl, (size_t)warp);
}

__global__ void __launch_bounds__(256) k_aggr4(const float* __restrict__ hin,
                                               const float* __restrict__ comp) {
    __shared__ float sc[RR * NBASE];
    int tid = threadIdx.x;
    if (tid < RR * NBASE) sc[tid] = comp[tid];
    __syncthreads();
    int warp = (blockIdx.x * blockDim.x + tid) >> 5;
    int lane = tid & 31;
    if (warp >= NQ) return;
    aggr_node(hin, sc, g_qo[warp], lane, g_y4h, g_y4l, (size_t)warp);
}

// ---------------- bf16x3 GEMM: ldmatrix A + fragment-ordered B ----------------
__device__ __forceinline__ void mma16(float* c, const uint32_t* a, const uint32_t* b) {
    asm("mma.sync.aligned.m16n8k16.row.col.f32.bf16.bf16.f32 "
        "{%0,%1,%2,%3}, {%4,%5,%6,%7}, {%8,%9}, {%0,%1,%2,%3};"
        : "+f"(c[0]), "+f"(c[1]), "+f"(c[2]), "+f"(c[3])
        : "r"(a[0]), "r"(a[1]), "r"(a[2]), "r"(a[3]), "r"(b[0]), "r"(b[1]));
}

__device__ __forceinline__ void ldsm4(uint32_t* r, uint32_t addr) {
    asm volatile("ldmatrix.sync.aligned.m8n8.x4.shared.b16 {%0,%1,%2,%3}, [%4];"
        : "=r"(r[0]), "=r"(r[1]), "=r"(r[2]), "=r"(r[3]) : "r"(addr));
}

__global__ void __launch_bounds__(512) k_gemm2(
    const uint32_t* __restrict__ A1h, const uint32_t* __restrict__ A1l, // [N x 64]
    const uint32_t* __restrict__ A2h, const uint32_t* __restrict__ A2l, // [M x 512]
    const uint32_t* __restrict__ Bh,  const uint32_t* __restrict__ Bl,  // fragment-ordered
    const int* __restrict__ rowmap, const float* __restrict__ cbias,
    float* __restrict__ Cout, uint32_t* __restrict__ Coh, uint32_t* __restrict__ Col,
    int relu, int ntiles)
{
    extern __shared__ uint32_t sm[];
    uint32_t smb = (uint32_t)__cvta_generic_to_shared(sm);

    int tid = threadIdx.x;
    int wid = tid >> 5, lane = tid & 31;
    int wm = wid >> 2, wn = wid & 3;         // 4x4 warps, warp tile 32x32
    int grp = lane >> 2, tig = lane & 3;

    int r = tid >> 2, q4 = (tid & 3) * 4;
    uint32_t arow_b[2];
#pragma unroll
    for (int mi = 0; mi < 2; mi++)
        arow_b[mi] = (uint32_t)(((wm * 32 + mi * 16 + (lane & 15)) * ASTRIDE) * 4
                                + ((lane & 16) ? 16 : 0));
    int bcol[4];
#pragma unroll
    for (int ni = 0; ni < 4; ni++)
        bcol[ni] = ((wn * 32 + ni * 8 + grp) * 8 + tig * 2);

    for (int tile = blockIdx.x; tile < ntiles; tile += gridDim.x) {
        int row0 = tile * 128;
        int gr = row0 + r;
        int ar = rowmap ? rowmap[gr] : gr;

        uint4 avh, avl, bvh, bvl;

        auto LOAD = [&](int ci) {
            if (ci < 4) {
                size_t ia = (size_t)ar * 64 + ci * 16 + q4;
                avh = __ldcs((const uint4*)(A1h + ia));
                avl = __ldcs((const uint4*)(A1l + ia));
            } else {
                size_t ia = (size_t)gr * 512 + (ci * 16 - 64) + q4;
                avh = __ldcs((const uint4*)(A2h + ia));
                avl = __ldcs((const uint4*)(A2l + ia));
            }
            size_t ib = (size_t)ci * 2048 + tid * 4;
            bvh = *(const uint4*)(Bh + ib);
            bvl = *(const uint4*)(Bl + ib);
        };
        auto STORE = [&](int st) {
            *(uint4*)(sm + st * A_PLANE + r * ASTRIDE + q4)          = avh;
            *(uint4*)(sm + OFF_AL + st * A_PLANE + r * ASTRIDE + q4) = avl;
            *(uint4*)(sm + OFF_BH + st * B_PLANE + tid * 4)          = bvh;
            *(uint4*)(sm + OFF_BL + st * B_PLANE + tid * 4)          = bvl;
        };

        float acc[2][4][4];
#pragma unroll
        for (int mi = 0; mi < 2; mi++)
#pragma unroll
            for (int ni = 0; ni < 4; ni++)
#pragma unroll
                for (int k = 0; k < 4; k++) acc[mi][ni][k] = 0.f;

        LOAD(0);
        STORE(0);
        __syncthreads();

        for (int ci = 0; ci < NCHUNK; ci++) {
            int st = ci & 1;
            if (ci + 1 < NCHUNK) LOAD(ci + 1);
            uint32_t baseAh = smb + (st * A_PLANE) * 4;
            uint32_t baseAl = smb + ((OFF_AL + st * A_PLANE)) * 4;
            const uint32_t* sBh = sm + OFF_BH + st * B_PLANE;
            const uint32_t* sBl = sm + OFF_BL + st * B_PLANE;
#pragma unroll
            for (int ks = 0; ks < 2; ks++) {
                uint32_t bh[4][2], bl[4][2];
#pragma unroll
                for (int ni = 0; ni < 4; ni++) {
                    uint2 t0 = *(const uint2*)(sBh + ks * 1024 + bcol[ni]);
                    bh[ni][0] = t0.x; bh[ni][1] = t0.y;
                    uint2 t1 = *(const uint2*)(sBl + ks * 1024 + bcol[ni]);
                    bl[ni][0] = t1.x; bl[ni][1] = t1.y;
                }
#pragma unroll
                for (int mi = 0; mi < 2; mi++) {
                    uint32_t ah[4], al[4];
                    ldsm4(ah, baseAh + arow_b[mi] + ks * 32);
                    ldsm4(al, baseAl + arow_b[mi] + ks * 32);
#pragma unroll
                    for (int ni = 0; ni < 4; ni++) {
                        mma16(acc[mi][ni], ah, bh[ni]);
                        mma16(acc[mi][ni], ah, bl[ni]);
                        mma16(acc[mi][ni], al, bh[ni]);
                    }
                }
            }
            if (ci + 1 < NCHUNK) STORE((ci + 1) & 1);
            __syncthreads();
        }

        // epilogue: + cbias, optional relu; fp32 out (cached) + packed split out (streamed)
#pragma unroll
        for (int mi = 0; mi < 2; mi++) {
#pragma unroll
            for (int ni = 0; ni < 4; ni++) {
                int gc = wn * 32 + ni * 8 + 2 * tig;
                int rr = row0 + wm * 32 + mi * 16 + grp;
                float b0 = __ldg(cbias + gc), b1 = __ldg(cbias + gc + 1);
                float c00 = acc[mi][ni][0] + b0, c01 = acc[mi][ni][1] + b1;
                float c10 = acc[mi][ni][2] + b0, c11 = acc[mi][ni][3] + b1;
                if (relu) {
                    c00 = fmaxf(c00, 0.f); c01 = fmaxf(c01, 0.f);
                    c10 = fmaxf(c10, 0.f); c11 = fmaxf(c11, 0.f);
                }
                *(float2*)(Cout + (size_t)rr * HH + gc) = make_float2(c00, c01);
                *(float2*)(Cout + (size_t)(rr + 8) * HH + gc) = make_float2(c10, c11);
                if (Coh) {
                    uint32_t hi, lo;
                    split2(c00, c01, hi, lo);
                    __stcs(&Coh[(size_t)rr * 64 + (gc >> 1)], hi);
                    __stcs(&Col[(size_t)rr * 64 + (gc >> 1)], lo);
                    split2(c10, c11, hi, lo);
                    __stcs(&Coh[(size_t)(rr + 8) * 64 + (gc >> 1)], hi);
                    __stcs(&Col[(size_t)(rr + 8) * 64 + (gc >> 1)], lo);
                }
            }
        }
    }
}

// ---------------- head ----------------
__global__ void k_head(const int* __restrict__ qr,
                       const float* __restrict__ rel, const float* __restrict__ w,
                       const float* __restrict__ b, float* __restrict__ out) {
    int warp = (blockIdx.x * blockDim.x + threadIdx.x) >> 5;
    int lane = threadIdx.x & 31;
    if (warp >= NQ) return;
    const float* hv = g_h4q + (size_t)warp * HH;
    const float* rv = rel + (size_t)qr[warp] * HH;
    float s0 = 0.f, s1 = 0.f;
#pragma unroll
    for (int i = 0; i < 4; i++) {
        int k = lane + 32 * i;
        float a = hv[k], c = rv[k];
        s0 += a * w[k * 2 + 0] + c * w[(HH + k) * 2 + 0];
        s1 += a * w[k * 2 + 1] + c * w[(HH + k) * 2 + 1];
    }
#pragma unroll
    for (int off = 16; off; off >>= 1) {
        s0 += __shfl_xor_sync(0xFFFFFFFFu, s0, off);
        s1 += __shfl_xor_sync(0xFFFFFFFFu, s1, off);
    }
    if (lane == 0) {
        out[warp * 2 + 0] = s0 + b[0];
        out[warp * 2 + 1] = s1 + b[1];
    }
}

// ---------------- launch ----------------
extern "C" void kernel_launch(void* const* d_in, const int* in_sizes, int n_in,
                              void* d_out, int out_size) {
    const float* x    = (const float*)d_in[0];
    const int*   ent  = (const int*)  d_in[1];
    const int*   esrc = (const int*)  d_in[2];
    const int*   edst = (const int*)  d_in[3];
    const int*   etyp = (const int*)  d_in[4];
    const int*   dq   = (const int*)  d_in[5];
    const int*   qr   = (const int*)  d_in[6];
    const int*   ptr  = (const int*)  d_in[7];
    const float* rel  = (const float*)d_in[24];
    const float* lw   = (const float*)d_in[25];
    const float* lb   = (const float*)d_in[26];
    float*       out  = (float*)d_out;

    void* p;
    cudaGetSymbolAddress(&p, g_h0);     float*    h0f = (float*)p;
    cudaGetSymbolAddress(&p, g_h1);     float*    h1f = (float*)p;
    cudaGetSymbolAddress(&p, g_hsp0h);  uint32_t* h0h = (uint32_t*)p;
    cudaGetSymbolAddress(&p, g_hsp0l);  uint32_t* h0l = (uint32_t*)p;
    cudaGetSymbolAddress(&p, g_hsp1h);  uint32_t* h1h = (uint32_t*)p;
    cudaGetSymbolAddress(&p, g_hsp1l);  uint32_t* h1l = (uint32_t*)p;
    cudaGetSymbolAddress(&p, g_yh);     uint32_t* yh  = (uint32_t*)p;
    cudaGetSymbolAddress(&p, g_yl);     uint32_t* yl  = (uint32_t*)p;
    cudaGetSymbolAddress(&p, g_y4h);    uint32_t* y4h = (uint32_t*)p;
    cudaGetSymbolAddress(&p, g_y4l);    uint32_t* y4l = (uint32_t*)p;
    cudaGetSymbolAddress(&p, g_h4q);    float*    h4q = (float*)p;
    cudaGetSymbolAddress(&p, g_Bsph);   uint32_t* bsh = (uint32_t*)p;
    cudaGetSymbolAddress(&p, g_Bspl);   uint32_t* bsl = (uint32_t*)p;
    cudaGetSymbolAddress(&p, g_qo);     int*      qop = (int*)p;

    cudaFuncSetAttribute(k_gemm2, cudaFuncAttributeMaxDynamicSharedMemorySize, SMEMSZ);

    k_zero<<<(NN * RR + NN + 255) / 256, 256>>>(dq, ptr);
    k_setup1<<<(NN * 64 + 255) / 256, 256>>>(x, ent, edst, etyp);
    k_scan1<<<NBLK, 1024>>>();
    k_fill<<<(EE + 255) / 256, 256>>>(edst);
    k_sortfin<<<(NN + 255) / 256, 256>>>(esrc, etyp);
    k_splitB<<<(4 * NPAIR * 128 + 255) / 256, 256>>>(
        (const float*)d_in[10], (const float*)d_in[8],
        (const float*)d_in[14], (const float*)d_in[12],
        (const float*)d_in[18], (const float*)d_in[16],
        (const float*)d_in[22], (const float*)d_in[20]);

    float*    hinf = h0f;  uint32_t* hinh = h0h;  uint32_t* hinl = h0l;
    float*    houtf = h1f; uint32_t* houth = h1h; uint32_t* houtl = h1l;
    for (int l = 0; l < 3; l++) {
        const float* comp = (const float*)d_in[9 + 4 * l];
        const float* cb   = (const float*)d_in[11 + 4 * l];
        k_aggr<<<NN / 8, 256>>>(hinf, comp);
        k_gemm2<<<GEMM_GRID, 512, SMEMSZ>>>(hinh, hinl, yh, yl,
                                            bsh + (size_t)l * BWORDS, bsl + (size_t)l * BWORDS,
                                            nullptr, cb, houtf, houth, houtl, 1, NN / 128);
        float* tf = hinf; hinf = houtf; houtf = tf;
        uint32_t* th = hinh; hinh = houth; houth = th;
        uint32_t* tl = hinl; hinl = houtl; houtl = tl;
    }
    // layer 4: only 512 query rows
    {
        const float* comp = (const float*)d_in[21];
        const float* cb   = (const float*)d_in[23];
        k_aggr4<<<NQ / 8, 256>>>(hinf, comp);
        k_gemm2<<<NQ / 128, 512, SMEMSZ>>>(hinh, hinl, y4h, y4l,
                                           bsh + 3 * (size_t)BWORDS, bsl + 3 * (size_t)BWORDS,
                                           qop, cb, h4q, nullptr, nullptr, 0, NQ / 128);
    }
    k_head<<<(NQ * 32 + 255) / 256, 256>>>(qr, rel, lw, lb, out);
}

// round 16
// speedup vs baseline: 1.2364x; 1.0736x over previous
#include <cuda_runtime.h>
#include <cuda_bf16.h>
#include <cstdint>

#define NN 51200
#define EE 819200
#define NQ 512
#define HH 128
#define RR 16
#define NBASE 8
#define CIN 128
#define YC 1024
#define KTOT 1152
#define NPAIR 576
#define NCHUNK 36
#define NBLK 50
#define SENTINEL (-2147483647)
#define GEMM_GRID 296
#define BWORDS 73728       /* per-layer fragment-ordered B: 36*2*128*8 words */

// smem (32-bit words): Ah/Al 2 stages x 128 rows x 20; Bh/Bl 2 stages x 2048 (fragment order)
#define ASTRIDE 20
#define A_PLANE 2560
#define B_PLANE 2048
#define OFF_AL  (2 * A_PLANE)
#define OFF_BH  (4 * A_PLANE)
#define OFF_BL  (4 * A_PLANE + 2 * B_PLANE)
#define SMEMSZ ((4 * A_PLANE + 4 * B_PLANE) * 4)   /* 73728 B */

#define CP_ASYNC16(dst, src) \
    asm volatile("cp.async.cg.shared.global [%0], [%1], 16;" :: "r"(dst), "l"(src))
#define CP_COMMIT() asm volatile("cp.async.commit_group;" ::: "memory")
#define CP_WAIT0()  asm volatile("cp.async.wait_group 0;" ::: "memory")

// ---------------- device scratch ----------------
__device__ float    g_h0[NN * CIN];
__device__ float    g_h1[NN * CIN];
__device__ uint32_t g_hsp0h[NN * 64];
__device__ uint32_t g_hsp0l[NN * 64];
__device__ uint32_t g_hsp1h[NN * 64];
__device__ uint32_t g_hsp1l[NN * 64];
__device__ uint32_t g_yh[(size_t)NN * 512];
__device__ uint32_t g_yl[(size_t)NN * 512];
__device__ uint32_t g_y4h[NQ * 512];
__device__ uint32_t g_y4l[NQ * 512];
__device__ float    g_h4q[NQ * HH];
__device__ uint32_t g_Bsph[4 * BWORDS];
__device__ uint32_t g_Bspl[4 * BWORDS];
__device__ int      g_cntdeg[NN * RR + NN];
__device__ int      g_rowptr[NN + 1];
__device__ int      g_cursor[NN];
__device__ int      g_eidx[EE];
__device__ int2     g_sw[EE];      // (src*RR+etype, weight bits)
__device__ int      g_qo[NQ];
__device__ int      g_scanpub[NBLK];

// ---------------- bf16 split helpers ----------------
__device__ __forceinline__ void split2(float a, float b, uint32_t& hi, uint32_t& lo) {
    __nv_bfloat16 ah = __float2bfloat16_rn(a), bh = __float2bfloat16_rn(b);
    float ar = a - __bfloat162float(ah), br = b - __bfloat162float(bh);
    __nv_bfloat16 al = __float2bfloat16_rn(ar), bl = __float2bfloat16_rn(br);
    hi = ((uint32_t)__bfloat16_as_ushort(bh) << 16) | __bfloat16_as_ushort(ah);
    lo = ((uint32_t)__bfloat16_as_ushort(bl) << 16) | __bfloat16_as_ushort(al);
}

// ---------------- zero counters + scan slots + qlist ----------------
__global__ void k_zero(const int* __restrict__ dq, const int* __restrict__ ptr) {
    int gid = blockIdx.x * blockDim.x + threadIdx.x;
    if (gid < NN * RR + NN) g_cntdeg[gid] = 0;
    if (gid < NBLK) g_scanpub[gid] = SENTINEL;
    if (gid < NQ) g_qo[gid] = dq[gid] + ptr[gid];
}

// ---------------- setup1: h0 fp32 + split, AND per-(dst,rel)/deg counts ----------------
__global__ void k_setup1(const float* __restrict__ x, const int* __restrict__ ent,
                         const int* __restrict__ edst, const int* __restrict__ etyp) {
    int gid = blockIdx.x * blockDim.x + threadIdx.x;
    if (gid < NN * 64) {
        int n = gid >> 6, pr = gid & 63;
        int j0 = 2 * pr, j1 = j0 + 1;
        int e = __ldg(ent + n);
        float v0 = (j0 < 64) ? __ldg(x + n * 64 + j0) : ((e == j0 - 64) ? 1.0f : 0.0f);
        float v1 = (j1 < 64) ? __ldg(x + n * 64 + j1) : ((e == j1 - 64) ? 1.0f : 0.0f);
        *(float2*)(g_h0 + n * CIN + j0) = make_float2(v0, v1);
        uint32_t hi, lo;
        split2(v0, v1, hi, lo);
        __stcs(&g_hsp0h[gid], hi);
        __stcs(&g_hsp0l[gid], lo);
    }
    if (gid < EE) {
        int d = edst[gid], t = etyp[gid];
        atomicAdd(&g_cntdeg[d * RR + t], 1);
        atomicAdd(&g_cntdeg[NN * RR + d], 1);
    }
}

// ---------------- chained exclusive scan over deg (50 blocks, all resident) ----------------
__global__ void k_scan1() {
    __shared__ int sd[1024];
    __shared__ int s_prev;
    int b = blockIdx.x, tid = threadIdx.x;
    int gid = b * 1024 + tid;
    int v = g_cntdeg[NN * RR + gid];
    sd[tid] = v;
    __syncthreads();
    for (int off = 1; off < 1024; off <<= 1) {
        int t = (tid >= off) ? sd[tid - off] : 0;
        __syncthreads();
        sd[tid] += t;
        __syncthreads();
    }
    int incl = sd[tid];
    int total = sd[1023];
    if (tid == 0) {
        int prev = 0;
        if (b > 0) {
            while ((prev = atomicAdd(&g_scanpub[b - 1], 0)) == SENTINEL) { }
        }
        s_prev = prev;
        __threadfence();
        atomicExch(&g_scanpub[b], prev + total);
    }
    __syncthreads();
    int e = s_prev + incl - v;
    g_rowptr[gid] = e;
    g_cursor[gid] = e;
    if (gid == 0) g_rowptr[NN] = EE;
}

__global__ void k_fill(const int* __restrict__ edst) {
    int e = blockIdx.x * blockDim.x + threadIdx.x;
    if (e >= EE) return;
    int pos = atomicAdd(&g_cursor[edst[e]], 1);
    g_eidx[pos] = e;
}

// deterministic per-bucket order: sort bucket by edge id (local-array fast path)
__global__ void k_sortfin(const int* __restrict__ esrc, const int* __restrict__ etyp) {
    int n = blockIdx.x * blockDim.x + threadIdx.x;
    if (n >= NN) return;
    int s = g_rowptr[n], t = g_rowptr[n + 1];
    int cnt = t - s;
    if (cnt <= 64) {
        int buf[64];
        for (int i = 0; i < cnt; i++) buf[i] = g_eidx[s + i];
        for (int i = 1; i < cnt; i++) {
            int v = buf[i];
            int j = i - 1;
            while (j >= 0 && buf[j] > v) { buf[j + 1] = buf[j]; j--; }
            buf[j + 1] = v;
        }
        for (int i = 0; i < cnt; i++) {
            int e  = buf[i];
            int et = etyp[e];
            int c  = g_cntdeg[n * RR + et];
            float w = 1.0f / (float)(c < 1 ? 1 : c);
            g_sw[s + i] = make_int2(esrc[e] * RR + et, __float_as_int(w));
        }
    } else {
        for (int i = s + 1; i < t; i++) {
            int v = g_eidx[i];
            int j = i - 1;
            while (j >= s && g_eidx[j] > v) { g_eidx[j + 1] = g_eidx[j]; j--; }
            g_eidx[j + 1] = v;
        }
        for (int i = s; i < t; i++) {
            int e  = g_eidx[i];
            int et = etyp[e];
            int c  = g_cntdeg[n * RR + et];
            float w = 1.0f / (float)(c < 1 ? 1 : c);
            g_sw[i] = make_int2(esrc[e] * RR + et, __float_as_int(w));
        }
    }
}

// ---------------- pre-split weights -> fragment-ordered packed bf16 pairs ----------------
__global__ void k_splitB(const float* __restrict__ r1, const float* __restrict__ b1,
                         const float* __restrict__ r2, const float* __restrict__ b2,
                         const float* __restrict__ r3, const float* __restrict__ b3,
                         const float* __restrict__ r4, const float* __restrict__ b4) {
    int gid = blockIdx.x * blockDim.x + threadIdx.x;
    if (gid >= 4 * NPAIR * 128) return;
    int l = gid / (NPAIR * 128);
    int rem = gid - l * (NPAIR * 128);
    int kp = rem >> 7, c = rem & 127;
    const float* root  = (l == 0) ? r1 : (l == 1) ? r2 : (l == 2) ? r3 : r4;
    const float* bases = (l == 0) ? b1 : (l == 1) ? b2 : (l == 2) ? b3 : b4;
    int k0 = 2 * kp, k1 = k0 + 1;
    float v0 = (k0 < 128) ? root[k0 * HH + c] : bases[(size_t)(k0 - 128) * HH + c];
    float v1 = (k1 < 128) ? root[k1 * HH + c] : bases[(size_t)(k1 - 128) * HH + c];
    uint32_t hi, lo;
    split2(v0, v1, hi, lo);
    int ci = kp >> 4, r16 = kp & 15;
    int ks = r16 >> 3, pp = r16 & 7;
    int slot = (pp < 4) ? (pp * 2) : ((pp - 4) * 2 + 1);
    size_t idx = (size_t)l * BWORDS + (((ci * 2 + ks) * 128 + c) * 8 + slot);
    g_Bsph[idx] = hi;
    g_Bspl[idx] = lo;
}

// ---------------- aggregate-first: y[n,b,:] = sum_e comp[et,b]*w*h[src,:] ----------------
#define AGGR_EDGE(sv, wv, vv)                                        \
    {                                                                \
        const float* cc = sc + ((sv) & 15) * NBASE;                  \
        _Pragma("unroll")                                            \
        for (int b = 0; b < NBASE; b++) {                            \
            float f = cc[b] * (wv);                                  \
            acc[b].x += f * (vv).x; acc[b].y += f * (vv).y;          \
            acc[b].z += f * (vv).z; acc[b].w += f * (vv).w;          \
        }                                                            \
    }

__device__ __forceinline__ void aggr_node(
    const float* __restrict__ hin, const float* __restrict__ sc,
    int n, int lane, uint32_t* __restrict__ yh, uint32_t* __restrict__ yl, size_t orow)
{
    int s = g_rowptr[n], e = g_rowptr[n + 1];
    float4 acc[NBASE];
#pragma unroll
    for (int b = 0; b < NBASE; b++) acc[b] = make_float4(0.f, 0.f, 0.f, 0.f);
    int i = s;
    int lo4 = lane << 2;
    for (; i + 8 <= e; i += 8) {
        int2 p0 = g_sw[i],     p1 = g_sw[i + 1], p2 = g_sw[i + 2], p3 = g_sw[i + 3];
        int2 p4 = g_sw[i + 4], p5 = g_sw[i + 5], p6 = g_sw[i + 6], p7 = g_sw[i + 7];
        float4 v0 = *(const float4*)(hin + (size_t)(p0.x >> 4) * HH + lo4);
        float4 v1 = *(const float4*)(hin + (size_t)(p1.x >> 4) * HH + lo4);
        float4 v2 = *(const float4*)(hin + (size_t)(p2.x >> 4) * HH + lo4);
        float4 v3 = *(const float4*)(hin + (size_t)(p3.x >> 4) * HH + lo4);
        float4 v4 = *(const float4*)(hin + (size_t)(p4.x >> 4) * HH + lo4);
        float4 v5 = *(const float4*)(hin + (size_t)(p5.x >> 4) * HH + lo4);
        float4 v6 = *(const float4*)(hin + (size_t)(p6.x >> 4) * HH + lo4);
        float4 v7 = *(const float4*)(hin + (size_t)(p7.x >> 4) * HH + lo4);
        AGGR_EDGE(p0.x, __int_as_float(p0.y), v0)
        AGGR_EDGE(p1.x, __int_as_float(p1.y), v1)
        AGGR_EDGE(p2.x, __int_as_float(p2.y), v2)
        AGGR_EDGE(p3.x, __int_as_float(p3.y), v3)
        AGGR_EDGE(p4.x, __int_as_float(p4.y), v4)
        AGGR_EDGE(p5.x, __int_as_float(p5.y), v5)
        AGGR_EDGE(p6.x, __int_as_float(p6.y), v6)
        AGGR_EDGE(p7.x, __int_as_float(p7.y), v7)
    }
    for (; i + 4 <= e; i += 4) {
        int2 p0 = g_sw[i], p1 = g_sw[i + 1], p2 = g_sw[i + 2], p3 = g_sw[i + 3];
        float4 v0 = *(const float4*)(hin + (size_t)(p0.x >> 4) * HH + lo4);
        float4 v1 = *(const float4*)(hin + (size_t)(p1.x >> 4) * HH + lo4);
        float4 v2 = *(const float4*)(hin + (size_t)(p2.x >> 4) * HH + lo4);
        float4 v3 = *(const float4*)(hin + (size_t)(p3.x >> 4) * HH + lo4);
        AGGR_EDGE(p0.x, __int_as_float(p0.y), v0)
        AGGR_EDGE(p1.x, __int_as_float(p1.y), v1)
        AGGR_EDGE(p2.x, __int_as_float(p2.y), v2)
        AGGR_EDGE(p3.x, __int_as_float(p3.y), v3)
    }
    for (; i < e; i++) {
        int2 p0 = g_sw[i];
        float4 v0 = *(const float4*)(hin + (size_t)(p0.x >> 4) * HH + lo4);
        AGGR_EDGE(p0.x, __int_as_float(p0.y), v0)
    }
    size_t base = orow * 512 + (lane << 1);
#pragma unroll
    for (int b = 0; b < NBASE; b++) {
        uint32_t h0, l0, h1, l1;
        split2(acc[b].x, acc[b].y, h0, l0);
        split2(acc[b].z, acc[b].w, h1, l1);
        __stcs((uint2*)(yh + base + b * 64), make_uint2(h0, h1));
        __stcs((uint2*)(yl + base + b * 64), make_uint2(l0, l1));
    }
}

__global__ void __launch_bounds__(256) k_aggr(const float* __restrict__ hin,
                                              const float* __restrict__ comp) {
    __shared__ float sc[RR * NBASE];
    int tid = threadIdx.x;
    if (tid < RR * NBASE) sc[tid] = comp[tid];
    __syncthreads();
    int warp = (blockIdx.x * blockDim.x + tid) >> 5;
    int lane = tid & 31;
    if (warp >= NN) return;
    aggr_node(hin, sc, warp, lane, g_yh, g_yl, (size_t)warp);
}

__global__ void __launch_bounds__(256) k_aggr4(const float* __restrict__ hin,
                                               const float* __restrict__ comp) {
    __shared__ float sc[RR * NBASE];
    int tid = threadIdx.x;
    if (tid < RR * NBASE) sc[tid] = comp[tid];
    __syncthreads();
    int warp = (blockIdx.x * blockDim.x + tid) >> 5;
    int lane = tid & 31;
    if (warp >= NQ) return;
    aggr_node(hin, sc, g_qo[warp], lane, g_y4h, g_y4l, (size_t)warp);
}

// ---------------- bf16x3 GEMM: cp.async staging (1 barrier/chunk) + ldmatrix A ----------------
__device__ __forceinline__ void mma16(float* c, const uint32_t* a, const uint32_t* b) {
    asm("mma.sync.aligned.m16n8k16.row.col.f32.bf16.bf16.f32 "
        "{%0,%1,%2,%3}, {%4,%5,%6,%7}, {%8,%9}, {%0,%1,%2,%3};"
        : "+f"(c[0]), "+f"(c[1]), "+f"(c[2]), "+f"(c[3])
        : "r"(a[0]), "r"(a[1]), "r"(a[2]), "r"(a[3]), "r"(b[0]), "r"(b[1]));
}

__device__ __forceinline__ void ldsm4(uint32_t* r, uint32_t addr) {
    asm volatile("ldmatrix.sync.aligned.m8n8.x4.shared.b16 {%0,%1,%2,%3}, [%4];"
        : "=r"(r[0]), "=r"(r[1]), "=r"(r[2]), "=r"(r[3]) : "r"(addr));
}

__global__ void __launch_bounds__(512, 2) k_gemm2(
    const uint32_t* __restrict__ A1h, const uint32_t* __restrict__ A1l, // [N x 64]
    const uint32_t* __restrict__ A2h, const uint32_t* __restrict__ A2l, // [M x 512]
    const uint32_t* __restrict__ Bh,  const uint32_t* __restrict__ Bl,  // fragment-ordered
    const int* __restrict__ rowmap, const float* __restrict__ cbias,
    float* __restrict__ Cout, uint32_t* __restrict__ Coh, uint32_t* __restrict__ Col,
    int relu, int ntiles)
{
    extern __shared__ uint32_t sm[];
    uint32_t smb = (uint32_t)__cvta_generic_to_shared(sm);

    int tid = threadIdx.x;
    int wid = tid >> 5, lane = tid & 31;
    int wm = wid >> 2, wn = wid & 3;         // 4x4 warps, warp tile 32x32
    int grp = lane >> 2, tig = lane & 3;

    int r = tid >> 2, q4 = (tid & 3) * 4;
    uint32_t arow_b[2];
#pragma unroll
    for (int mi = 0; mi < 2; mi++)
        arow_b[mi] = (uint32_t)(((wm * 32 + mi * 16 + (lane & 15)) * ASTRIDE) * 4
                                + ((lane & 16) ? 16 : 0));
    int bcol[4];
#pragma unroll
    for (int ni = 0; ni < 4; ni++)
        bcol[ni] = ((wn * 32 + ni * 8 + grp) * 8 + tig * 2);

    for (int tile = blockIdx.x; tile < ntiles; tile += gridDim.x) {
        int row0 = tile * 128;
        int gr = row0 + r;
        int ar = rowmap ? rowmap[gr] : gr;

        auto ISSUE = [&](int ci) {
            int st = ci & 1;
            const uint32_t *pah, *pal;
            if (ci < 4) {
                size_t ia = (size_t)ar * 64 + ci * 16 + q4;
                pah = A1h + ia; pal = A1l + ia;
            } else {
                size_t ia = (size_t)gr * 512 + (ci * 16 - 64) + q4;
                pah = A2h + ia; pal = A2l + ia;
            }
            CP_ASYNC16(smb + (st * A_PLANE + r * ASTRIDE + q4) * 4, pah);
            CP_ASYNC16(smb + ((OFF_AL + st * A_PLANE) + r * ASTRIDE + q4) * 4, pal);
            size_t ib = (size_t)ci * 2048 + tid * 4;
            CP_ASYNC16(smb + ((OFF_BH + st * B_PLANE) + tid * 4) * 4, Bh + ib);
            CP_ASYNC16(smb + ((OFF_BL + st * B_PLANE) + tid * 4) * 4, Bl + ib);
            CP_COMMIT();
        };

        float acc[2][4][4];
#pragma unroll
        for (int mi = 0; mi < 2; mi++)
#pragma unroll
            for (int ni = 0; ni < 4; ni++)
#pragma unroll
                for (int k = 0; k < 4; k++) acc[mi][ni][k] = 0.f;

        ISSUE(0);
        CP_WAIT0();
        __syncthreads();

        for (int ci = 0; ci < NCHUNK; ci++) {
            int st = ci & 1;
            if (ci + 1 < NCHUNK) ISSUE(ci + 1);          // prefetch into other stage
            uint32_t baseAh = smb + (st * A_PLANE) * 4;
            uint32_t baseAl = smb + ((OFF_AL + st * A_PLANE)) * 4;
            const uint32_t* sBh = sm + OFF_BH + st * B_PLANE;
            const uint32_t* sBl = sm + OFF_BL + st * B_PLANE;
#pragma unroll
            for (int ks = 0; ks < 2; ks++) {
                uint32_t bh[4][2], bl[4][2];
#pragma unroll
                for (int ni = 0; ni < 4; ni++) {
                    uint2 t0 = *(const uint2*)(sBh + ks * 1024 + bcol[ni]);
                    bh[ni][0] = t0.x; bh[ni][1] = t0.y;
                    uint2 t1 = *(const uint2*)(sBl + ks * 1024 + bcol[ni]);
                    bl[ni][0] = t1.x; bl[ni][1] = t1.y;
                }
#pragma unroll
                for (int mi = 0; mi < 2; mi++) {
                    uint32_t ah[4], al[4];
                    ldsm4(ah, baseAh + arow_b[mi] + ks * 32);
                    ldsm4(al, baseAl + arow_b[mi] + ks * 32);
#pragma unroll
                    for (int ni = 0; ni < 4; ni++) {
                        mma16(acc[mi][ni], ah, bh[ni]);
                        mma16(acc[mi][ni], ah, bl[ni]);
                        mma16(acc[mi][ni], al, bh[ni]);
                    }
                }
            }
            if (ci + 1 < NCHUNK) CP_WAIT0();             // prefetch had full compute to land
            __syncthreads();
        }

        // epilogue: + cbias, optional relu; fp32 out + packed split out (streamed)
#pragma unroll
        for (int mi = 0; mi < 2; mi++) {
#pragma unroll
            for (int ni = 0; ni < 4; ni++) {
                int gc = wn * 32 + ni * 8 + 2 * tig;
                int rr = row0 + wm * 32 + mi * 16 + grp;
                float b0 = __ldg(cbias + gc), b1 = __ldg(cbias + gc + 1);
                float c00 = acc[mi][ni][0] + b0, c01 = acc[mi][ni][1] + b1;
                float c10 = acc[mi][ni][2] + b0, c11 = acc[mi][ni][3] + b1;
                if (relu) {
                    c00 = fmaxf(c00, 0.f); c01 = fmaxf(c01, 0.f);
                    c10 = fmaxf(c10, 0.f); c11 = fmaxf(c11, 0.f);
                }
                *(float2*)(Cout + (size_t)rr * HH + gc) = make_float2(c00, c01);
                *(float2*)(Cout + (size_t)(rr + 8) * HH + gc) = make_float2(c10, c11);
                if (Coh) {
                    uint32_t hi, lo;
                    split2(c00, c01, hi, lo);
                    __stcs(&Coh[(size_t)rr * 64 + (gc >> 1)], hi);
                    __stcs(&Col[(size_t)rr * 64 + (gc >> 1)], lo);
                    split2(c10, c11, hi, lo);
                    __stcs(&Coh[(size_t)(rr + 8) * 64 + (gc >> 1)], hi);
                    __stcs(&Col[(size_t)(rr + 8) * 64 + (gc >> 1)], lo);
                }
            }
        }
    }
}

// ---------------- head ----------------
__global__ void k_head(const int* __restrict__ qr,
                       const float* __restrict__ rel, const float* __restrict__ w,
                       const float* __restrict__ b, float* __restrict__ out) {
    int warp = (blockIdx.x * blockDim.x + threadIdx.x) >> 5;
    int lane = threadIdx.x & 31;
    if (warp >= NQ) return;
    const float* hv = g_h4q + (size_t)warp * HH;
    const float* rv = rel + (size_t)qr[warp] * HH;
    float s0 = 0.f, s1 = 0.f;
#pragma unroll
    for (int i = 0; i < 4; i++) {
        int k = lane + 32 * i;
        float a = hv[k], c = rv[k];
        s0 += a * w[k * 2 + 0] + c * w[(HH + k) * 2 + 0];
        s1 += a * w[k * 2 + 1] + c * w[(HH + k) * 2 + 1];
    }
#pragma unroll
    for (int off = 16; off; off >>= 1) {
        s0 += __shfl_xor_sync(0xFFFFFFFFu, s0, off);
        s1 += __shfl_xor_sync(0xFFFFFFFFu, s1, off);
    }
    if (lane == 0) {
        out[warp * 2 + 0] = s0 + b[0];
        out[warp * 2 + 1] = s1 + b[1];
    }
}

// ---------------- launch ----------------
extern "C" void kernel_launch(void* const* d_in, const int* in_sizes, int n_in,
                              void* d_out, int out_size) {
    const float* x    = (const float*)d_in[0];
    const int*   ent  = (const int*)  d_in[1];
    const int*   esrc = (const int*)  d_in[2];
    const int*   edst = (const int*)  d_in[3];
    const int*   etyp = (const int*)  d_in[4];
    const int*   dq   = (const int*)  d_in[5];
    const int*   qr   = (const int*)  d_in[6];
    const int*   ptr  = (const int*)  d_in[7];
    const float* rel  = (const float*)d_in[24];
    const float* lw   = (const float*)d_in[25];
    const float* lb   = (const float*)d_in[26];
    float*       out  = (float*)d_out;

    void* p;
    cudaGetSymbolAddress(&p, g_h0);     float*    h0f = (float*)p;
    cudaGetSymbolAddress(&p, g_h1);     float*    h1f = (float*)p;
    cudaGetSymbolAddress(&p, g_hsp0h);  uint32_t* h0h = (uint32_t*)p;
    cudaGetSymbolAddress(&p, g_hsp0l);  uint32_t* h0l = (uint32_t*)p;
    cudaGetSymbolAddress(&p, g_hsp1h);  uint32_t* h1h = (uint32_t*)p;
    cudaGetSymbolAddress(&p, g_hsp1l);  uint32_t* h1l = (uint32_t*)p;
    cudaGetSymbolAddress(&p, g_yh);     uint32_t* yh  = (uint32_t*)p;
    cudaGetSymbolAddress(&p, g_yl);     uint32_t* yl  = (uint32_t*)p;
    cudaGetSymbolAddress(&p, g_y4h);    uint32_t* y4h = (uint32_t*)p;
    cudaGetSymbolAddress(&p, g_y4l);    uint32_t* y4l = (uint32_t*)p;
    cudaGetSymbolAddress(&p, g_h4q);    float*    h4q = (float*)p;
    cudaGetSymbolAddress(&p, g_Bsph);   uint32_t* bsh = (uint32_t*)p;
    cudaGetSymbolAddress(&p, g_Bspl);   uint32_t* bsl = (uint32_t*)p;
    cudaGetSymbolAddress(&p, g_qo);     int*      qop = (int*)p;

    cudaFuncSetAttribute(k_gemm2, cudaFuncAttributeMaxDynamicSharedMemorySize, SMEMSZ);

    k_zero<<<(NN * RR + NN + 255) / 256, 256>>>(dq, ptr);
    k_setup1<<<(NN * 64 + 255) / 256, 256>>>(x, ent, edst, etyp);
    k_scan1<<<NBLK, 1024>>>();
    k_fill<<<(EE + 255) / 256, 256>>>(edst);
    k_sortfin<<<(NN + 255) / 256, 256>>>(esrc, etyp);
    k_splitB<<<(4 * NPAIR * 128 + 255) / 256, 256>>>(
        (const float*)d_in[10], (const float*)d_in[8],
        (const float*)d_in[14], (const float*)d_in[12],
        (const float*)d_in[18], (const float*)d_in[16],
        (const float*)d_in[22], (const float*)d_in[20]);

    float*    hinf = h0f;  uint32_t* hinh = h0h;  uint32_t* hinl = h0l;
    float*    houtf = h1f; uint32_t* houth = h1h; uint32_t* houtl = h1l;
    for (int l = 0; l < 3; l++) {
        const float* comp = (const float*)d_in[9 + 4 * l];
        const float* cb   = (const float*)d_in[11 + 4 * l];
        k_aggr<<<NN / 8, 256>>>(hinf, comp);
        k_gemm2<<<GEMM_GRID, 512, SMEMSZ>>>(hinh, hinl, yh, yl,
                                            bsh + (size_t)l * BWORDS, bsl + (size_t)l * BWORDS,
                                            nullptr, cb, houtf, houth, houtl, 1, NN / 128);
        float* tf = hinf; hinf = houtf; houtf = tf;
        uint32_t* th = hinh; hinh = houth; houth = th;
        uint32_t* tl = hinl; hinl = houtl; houtl = tl;
    }
    // layer 4: only 512 query rows
    {
        const float* comp = (const float*)d_in[21];
        const float* cb   = (const float*)d_in[23];
        k_aggr4<<<NQ / 8, 256>>>(hinf, comp);
        k_gemm2<<<NQ / 128, 512, SMEMSZ>>>(hinh, hinl, y4h, y4l,
                                           bsh + 3 * (size_t)BWORDS, bsl + 3 * (size_t)BWORDS,
                                           qop, cb, h4q, nullptr, nullptr, 0, NQ / 128);
    }
    k_head<<<(NQ * 32 + 255) / 256, 256>>>(qr, rel, lw, lb, out);
}